// round 11
// baseline (speedup 1.0000x reference)
#include <cuda_runtime.h>
#include <cuda_bf16.h>
#include <math.h>
#include <stdint.h>

// ----------------------------------------------------------------------------
// Problem constants: B=8, T=1024, D=1024, H=16, HD=64.  M = B*T = 8192.
// ----------------------------------------------------------------------------
#define M_ROWS 8192
#define DMODEL 1024
#define D3     3072
#define DFF    4096
#define NHEAD  16
#define HDIM   64
#define SEQ    1024

// ----------------------------------------------------------------------------
// Scratch (device globals -- no cudaMalloc allowed)
// ----------------------------------------------------------------------------
__device__ __nv_bfloat16 g_qkv_h[M_ROWS * D3];       // QKV split hi
__device__ __nv_bfloat16 g_qkv_l[M_ROWS * D3];       // QKV split lo
__device__ float g_tmp[M_ROWS * DMODEL];             // fp32 pre-LN buffers
__device__ float g_x1 [M_ROWS * DMODEL];
__device__ __nv_bfloat16 g_act_h[M_ROWS * DMODEL];   // activation hi (X / ctx / x1)
__device__ __nv_bfloat16 g_act_l[M_ROWS * DMODEL];   // activation lo
__device__ __nv_bfloat16 g_ffh_h[M_ROWS * DFF];      // FF1 out hi
__device__ __nv_bfloat16 g_ffh_l[M_ROWS * DFF];      // FF1 out lo
// weights, transposed to [N,K], split hi/lo
__device__ __nv_bfloat16 g_wqkv_h[DMODEL * D3];
__device__ __nv_bfloat16 g_wqkv_l[DMODEL * D3];
__device__ __nv_bfloat16 g_wout_h[DMODEL * DMODEL];
__device__ __nv_bfloat16 g_wout_l[DMODEL * DMODEL];
__device__ __nv_bfloat16 g_wff1_h[DMODEL * DFF];
__device__ __nv_bfloat16 g_wff1_l[DMODEL * DFF];
__device__ __nv_bfloat16 g_wff2_h[DFF * DMODEL];
__device__ __nv_bfloat16 g_wff2_l[DFF * DMODEL];

// ----------------------------------------------------------------------------
// PTX helpers (compute_103-baseline legal: cp.async / ldmatrix / mma.sync)
// ----------------------------------------------------------------------------
__device__ __forceinline__ uint32_t smem_to_u32(const void* smem_ptr) {
    uint32_t addr;
    asm("{ .reg .u64 tmp; cvta.to.shared.u64 tmp, %1; cvt.u32.u64 %0, tmp; }"
        : "=r"(addr) : "l"(smem_ptr));
    return addr;
}

__device__ __forceinline__ void cp16(uint32_t smem_addr, const void* gptr) {
    asm volatile("cp.async.cg.shared.global [%0], [%1], 16;"
                 :: "r"(smem_addr), "l"(gptr));
}
#define CP_COMMIT() asm volatile("cp.async.commit_group;" ::: "memory")
#define CP_WAIT1()  asm volatile("cp.async.wait_group 1;" ::: "memory")

__device__ __forceinline__ void ldsm4(uint32_t* d, uint32_t addr) {
    asm volatile("ldmatrix.sync.aligned.m8n8.x4.shared.b16 {%0,%1,%2,%3}, [%4];"
        : "=r"(d[0]), "=r"(d[1]), "=r"(d[2]), "=r"(d[3]) : "r"(addr));
}
__device__ __forceinline__ void ldsm2(uint32_t* d, uint32_t addr) {
    asm volatile("ldmatrix.sync.aligned.m8n8.x2.shared.b16 {%0,%1}, [%2];"
        : "=r"(d[0]), "=r"(d[1]) : "r"(addr));
}
__device__ __forceinline__ void ldsm2t(uint32_t* d, uint32_t addr) {
    asm volatile("ldmatrix.sync.aligned.m8n8.x2.trans.shared.b16 {%0,%1}, [%2];"
        : "=r"(d[0]), "=r"(d[1]) : "r"(addr));
}

__device__ __forceinline__ void mma16816(float* c, const uint32_t* a, const uint32_t* b) {
    asm volatile("mma.sync.aligned.m16n8k16.row.col.f32.bf16.bf16.f32 "
        "{%0,%1,%2,%3}, {%4,%5,%6,%7}, {%8,%9}, {%0,%1,%2,%3};"
        : "+f"(c[0]), "+f"(c[1]), "+f"(c[2]), "+f"(c[3])
        : "r"(a[0]), "r"(a[1]), "r"(a[2]), "r"(a[3]), "r"(b[0]), "r"(b[1]));
}

// ----------------------------------------------------------------------------
// Split: fp32 -> (bf16 hi, bf16 lo) so x ~= hi + lo
// ----------------------------------------------------------------------------
__device__ __forceinline__ void split2(float a, float b, uint32_t& h, uint32_t& l) {
    __nv_bfloat16 ha = __float2bfloat16(a);
    __nv_bfloat16 hb = __float2bfloat16(b);
    __nv_bfloat16 la = __float2bfloat16(a - __bfloat162float(ha));
    __nv_bfloat16 lb = __float2bfloat16(b - __bfloat162float(hb));
    __nv_bfloat162 hp(ha, hb), lp(la, lb);
    h = *(uint32_t*)&hp; l = *(uint32_t*)&lp;
}

__global__ __launch_bounds__(256) void convert_split_kernel(
    const float* __restrict__ x, __nv_bfloat16* __restrict__ h,
    __nv_bfloat16* __restrict__ l, int n4)
{
    int i = blockIdx.x * 256 + threadIdx.x;
    if (i >= n4) return;
    float4 v = ((const float4*)x)[i];
    uint32_t h0, l0, h1, l1;
    split2(v.x, v.y, h0, l0);
    split2(v.z, v.w, h1, l1);
    ((uint2*)h)[i] = make_uint2(h0, h1);
    ((uint2*)l)[i] = make_uint2(l0, l1);
}

// W [K,N] fp32 row-major -> Wt hi/lo [N,K] bf16 (32x32 tiles)
__global__ __launch_bounds__(256) void transpose_split_kernel(
    const float* __restrict__ W, __nv_bfloat16* __restrict__ h,
    __nv_bfloat16* __restrict__ l, int K, int N)
{
    __shared__ float t[32][33];
    const int tx = threadIdx.x;
    const int ty = threadIdx.y;
    const int k0 = blockIdx.y * 32;
    const int n0 = blockIdx.x * 32;
    #pragma unroll
    for (int r = 0; r < 4; r++)
        t[ty * 4 + r][tx] = W[(size_t)(k0 + ty * 4 + r) * N + n0 + tx];
    __syncthreads();
    #pragma unroll
    for (int r = 0; r < 4; r++) {
        int n = n0 + ty * 4 + r;
        float v = t[tx][ty * 4 + r];
        __nv_bfloat16 hv = __float2bfloat16(v);
        __nv_bfloat16 lv = __float2bfloat16(v - __bfloat162float(hv));
        h[(size_t)n * K + k0 + tx] = hv;
        l[(size_t)n * K + k0 + tx] = lv;
    }
}

// ----------------------------------------------------------------------------
// mma.sync split-bf16 GEMM:  C[M,N] = A[M,K] @ Bt[N,K]^T + bias (+ epilogue)
//   A ~ Ah + Al (bf16 [M,K]);  B ~ Bh + Bl (bf16 [N,K]).
//   A*B ~= Ah*Bh + Ah*Bl + Al*Bh  (fp32 accumulation).
// Tile: 128x256, BK=32, 256 threads (8 warps, 2x4 grid, each 64x64),
// 3-stage cp.async.  Smem rows padded to 80 B -> conflict-free ldmatrix.
// EPI: 0 = bias -> fp32;  1 = bias + residual -> fp32;
//      2 = bias + exact GELU -> split bf16;  3 = bias -> split bf16
// ----------------------------------------------------------------------------
#define BM 128
#define BN 256
#define BK 32
#define ROWB 80
#define AH_OFF 0
#define AL_OFF 10240
#define BH_OFF 20480
#define BL_OFF 40960
#define STAGE_BYTES 61440
#define GEMM_SMEM (3 * STAGE_BYTES)   // 184320

__device__ __forceinline__ float gelu_exact(float x) {
    return 0.5f * x * (1.0f + erff(x * 0.70710678118654752440f));
}

template <int EPI>
__global__ __launch_bounds__(256) void gemm_mma(
    const __nv_bfloat16* __restrict__ Ah, const __nv_bfloat16* __restrict__ Al,
    const __nv_bfloat16* __restrict__ Bh, const __nv_bfloat16* __restrict__ Bl,
    const float* __restrict__ bias, const float* __restrict__ res,
    float* __restrict__ C, __nv_bfloat16* __restrict__ Ch,
    __nv_bfloat16* __restrict__ Cl, int N, int K)
{
    extern __shared__ char smem[];
    const uint32_t sbase = smem_to_u32(smem);
    const int tid  = threadIdx.x;
    const int wid  = tid >> 5;
    const int lane = tid & 31;
    const int m0 = blockIdx.y * BM;
    const int n0 = blockIdx.x * BN;

    // A loader: 2 threads/row, 2 chunks each; B loader: 1 thread/row, 4 chunks
    const int rA = tid >> 1;
    const int cA = (tid & 1) * 2;

    // warp tile 64x64: wm in {0,64}, wn in {0,64,128,192}
    const int wm = (wid & 1) * 64;
    const int wn = (wid >> 1) * 64;

    float acc[4][8][4];
    #pragma unroll
    for (int i = 0; i < 4; i++)
        #pragma unroll
        for (int j = 0; j < 8; j++)
            #pragma unroll
            for (int k = 0; k < 4; k++) acc[i][j][k] = 0.0f;

    const int KT = K / BK;

    auto load_stage = [&](int it, int s) {
        const int kc = it * BK;
        const uint32_t st = sbase + s * STAGE_BYTES;
        // A
        const uint32_t sa = st + rA * ROWB + cA * 16;
        const size_t ga = (size_t)(m0 + rA) * K + kc + cA * 8;
        cp16(sa + AH_OFF,      Ah + ga);
        cp16(sa + AH_OFF + 16, Ah + ga + 8);
        cp16(sa + AL_OFF,      Al + ga);
        cp16(sa + AL_OFF + 16, Al + ga + 8);
        // B
        const uint32_t sbb = st + tid * ROWB;
        const size_t gb = (size_t)(n0 + tid) * K + kc;
        #pragma unroll
        for (int c = 0; c < 4; c++) {
            cp16(sbb + BH_OFF + c * 16, Bh + gb + c * 8);
            cp16(sbb + BL_OFF + c * 16, Bl + gb + c * 8);
        }
    };

    load_stage(0, 0); CP_COMMIT();
    load_stage(1, 1); CP_COMMIT();

    for (int it = 0; it < KT; it++) {
        CP_WAIT1();
        __syncthreads();
        const int nx = it + 2;
        if (nx < KT) load_stage(nx, nx % 3);
        CP_COMMIT();

        const uint32_t st = sbase + (it % 3) * STAGE_BYTES;
        #pragma unroll
        for (int ks = 0; ks < 2; ks++) {
            const int kb  = (ks * 16 + (lane >> 4) * 8) * 2;
            const int kbB = (ks * 16 + ((lane >> 3) & 1) * 8) * 2;
            uint32_t a_h[4][4], a_l[4][4];
            #pragma unroll
            for (int mf = 0; mf < 4; mf++) {
                uint32_t ra = st + (wm + mf * 16 + (lane & 15)) * ROWB + kb;
                ldsm4(a_h[mf], ra + AH_OFF);
                ldsm4(a_l[mf], ra + AL_OFF);
            }
            #pragma unroll
            for (int nf = 0; nf < 8; nf++) {
                uint32_t rb = st + (wn + nf * 8 + (lane & 7)) * ROWB + kbB;
                uint32_t b_h[2], b_l[2];
                ldsm2(b_h, rb + BH_OFF);
                ldsm2(b_l, rb + BL_OFF);
                #pragma unroll
                for (int mf = 0; mf < 4; mf++) {
                    mma16816(acc[mf][nf], a_h[mf], b_h);
                    mma16816(acc[mf][nf], a_h[mf], b_l);
                    mma16816(acc[mf][nf], a_l[mf], b_h);
                }
            }
        }
    }

    #pragma unroll
    for (int mf = 0; mf < 4; mf++) {
        const int m = m0 + wm + mf * 16 + (lane >> 2);
        #pragma unroll
        for (int nf = 0; nf < 8; nf++) {
            const int n = n0 + wn + nf * 8 + (lane & 3) * 2;
            float2 bv = *(const float2*)(bias + n);
            float* a = acc[mf][nf];
            float v0 = a[0] + bv.x, v1 = a[1] + bv.y;
            float v2 = a[2] + bv.x, v3 = a[3] + bv.y;
            if (EPI == 1) {
                float2 r0 = *(const float2*)(res + (size_t)m * N + n);
                float2 r1 = *(const float2*)(res + (size_t)(m + 8) * N + n);
                v0 += r0.x; v1 += r0.y; v2 += r1.x; v3 += r1.y;
            }
            if (EPI == 2) {
                v0 = gelu_exact(v0); v1 = gelu_exact(v1);
                v2 = gelu_exact(v2); v3 = gelu_exact(v3);
            }
            if (EPI >= 2) {
                uint32_t h0, l0, h1, l1;
                split2(v0, v1, h0, l0);
                split2(v2, v3, h1, l1);
                *(uint32_t*)(Ch + (size_t)m * N + n)       = h0;
                *(uint32_t*)(Cl + (size_t)m * N + n)       = l0;
                *(uint32_t*)(Ch + (size_t)(m + 8) * N + n) = h1;
                *(uint32_t*)(Cl + (size_t)(m + 8) * N + n) = l1;
            } else {
                *(float2*)(C + (size_t)m * N + n)       = make_float2(v0, v1);
                *(float2*)(C + (size_t)(m + 8) * N + n) = make_float2(v2, v3);
            }
        }
    }
}

// ----------------------------------------------------------------------------
// Tensor-core flash attention (split bf16).
// CTA: 64 q rows x one (b,h); 4 warps x 16 q rows; K tiles of 64 keys.
// S = Qh*Kh + Qh*Kl + Ql*Kh ; softmax in mma layout ; P split hi/lo ;
// O += (Ph+Pl)*Vh  (exact-P x bf16-V; Vl term dropped, error ~1e-4).
// Emits ctx directly as split bf16 (oh, ol).
// ----------------------------------------------------------------------------
#define AROW 144                       // smem row stride bytes (64 halves + pad)
#define AQ_BYTES (64 * AROW)           // 9216 per 64x64 tile
#define AST (3 * AQ_BYTES)             // stage: Kh,Kl,Vh = 27648
#define ATT_SMEM (2 * AQ_BYTES + 2 * AST)  // 73728

__global__ __launch_bounds__(128) void attn_mma(
    const __nv_bfloat16* __restrict__ qh, const __nv_bfloat16* __restrict__ ql,
    __nv_bfloat16* __restrict__ oh, __nv_bfloat16* __restrict__ ol)
{
    extern __shared__ char smem[];
    const uint32_t sb = smem_to_u32(smem);
    const int tid  = threadIdx.x;
    const int w    = tid >> 5;
    const int lane = tid & 31;
    const int bh = blockIdx.y;
    const int b  = bh >> 4;
    const int h  = bh & 15;
    const int q0 = blockIdx.x * 64;

    const uint32_t QHs = sb;
    const uint32_t QLs = sb + AQ_BYTES;

    const int r  = tid >> 1;           // 0..63
    const int cb = (tid & 1) * 4;      // chunk base (16B chunks)

    // Q tile loads (with group 0)
    {
        const size_t g = (size_t)(b * SEQ + q0 + r) * D3 + h * HDIM + cb * 8;
        const uint32_t o = r * AROW + cb * 16;
        #pragma unroll
        for (int c = 0; c < 4; c++) {
            cp16(QHs + o + c * 16, qh + g + c * 8);
            cp16(QLs + o + c * 16, ql + g + c * 8);
        }
    }
    auto load_kv = [&](int kt, int s) {
        const uint32_t st = sb + 2 * AQ_BYTES + s * AST;
        const size_t gk = (size_t)(b * SEQ + kt * 64 + r) * D3 + DMODEL + h * HDIM + cb * 8;
        const size_t gv = gk + DMODEL;
        const uint32_t o = r * AROW + cb * 16;
        #pragma unroll
        for (int c = 0; c < 4; c++) {
            cp16(st + o + c * 16,                 qh + gk + c * 8);
            cp16(st + AQ_BYTES + o + c * 16,      ql + gk + c * 8);
            cp16(st + 2 * AQ_BYTES + o + c * 16,  qh + gv + c * 8);
        }
    };
    load_kv(0, 0); CP_COMMIT();
    load_kv(1, 1); CP_COMMIT();

    uint32_t qfh[4][4], qfl[4][4];
    float O[8][4];
    #pragma unroll
    for (int i = 0; i < 8; i++)
        #pragma unroll
        for (int j = 0; j < 4; j++) O[i][j] = 0.0f;
    float m0 = -1e30f, m1 = -1e30f, l0 = 0.0f, l1 = 0.0f;

    for (int kt = 0; kt < SEQ / 64; kt++) {
        CP_WAIT1();
        __syncthreads();
        if (kt == 0) {
            #pragma unroll
            for (int kf = 0; kf < 4; kf++) {
                uint32_t qa = QHs + (w * 16 + (lane & 15)) * AROW + kf * 32 + (lane >> 4) * 16;
                ldsm4(qfh[kf], qa);
                ldsm4(qfl[kf], qa + AQ_BYTES);
            }
        }
        const uint32_t st = sb + 2 * AQ_BYTES + (kt & 1) * AST;

        // ---- S = Q K^T  (warp: 16q x 64k) ----
        float s[8][4];
        #pragma unroll
        for (int i = 0; i < 8; i++)
            #pragma unroll
            for (int j = 0; j < 4; j++) s[i][j] = 0.0f;
        #pragma unroll
        for (int kf = 0; kf < 4; kf++) {
            #pragma unroll
            for (int nf = 0; nf < 8; nf++) {
                uint32_t ka = st + (nf * 8 + (lane & 7)) * AROW + kf * 32 + ((lane >> 3) & 1) * 16;
                uint32_t b_h[2], b_l[2];
                ldsm2(b_h, ka);
                ldsm2(b_l, ka + AQ_BYTES);
                mma16816(s[nf], qfh[kf], b_h);
                mma16816(s[nf], qfh[kf], b_l);
                mma16816(s[nf], qfl[kf], b_h);
            }
        }

        // ---- online softmax in mma layout ----
        float mx0 = -1e30f, mx1 = -1e30f;
        #pragma unroll
        for (int nf = 0; nf < 8; nf++) {
            s[nf][0] *= 0.125f; s[nf][1] *= 0.125f;
            s[nf][2] *= 0.125f; s[nf][3] *= 0.125f;
            mx0 = fmaxf(mx0, fmaxf(s[nf][0], s[nf][1]));
            mx1 = fmaxf(mx1, fmaxf(s[nf][2], s[nf][3]));
        }
        mx0 = fmaxf(mx0, __shfl_xor_sync(0xffffffffu, mx0, 1));
        mx0 = fmaxf(mx0, __shfl_xor_sync(0xffffffffu, mx0, 2));
        mx1 = fmaxf(mx1, __shfl_xor_sync(0xffffffffu, mx1, 1));
        mx1 = fmaxf(mx1, __shfl_xor_sync(0xffffffffu, mx1, 2));
        float mn0 = fmaxf(m0, mx0), mn1 = fmaxf(m1, mx1);
        float cr0 = __expf(m0 - mn0), cr1 = __expf(m1 - mn1);
        float sm0 = 0.0f, sm1 = 0.0f;
        #pragma unroll
        for (int nf = 0; nf < 8; nf++) {
            s[nf][0] = __expf(s[nf][0] - mn0); sm0 += s[nf][0];
            s[nf][1] = __expf(s[nf][1] - mn0); sm0 += s[nf][1];
            s[nf][2] = __expf(s[nf][2] - mn1); sm1 += s[nf][2];
            s[nf][3] = __expf(s[nf][3] - mn1); sm1 += s[nf][3];
        }
        sm0 += __shfl_xor_sync(0xffffffffu, sm0, 1);
        sm0 += __shfl_xor_sync(0xffffffffu, sm0, 2);
        sm1 += __shfl_xor_sync(0xffffffffu, sm1, 1);
        sm1 += __shfl_xor_sync(0xffffffffu, sm1, 2);
        l0 = l0 * cr0 + sm0; m0 = mn0;
        l1 = l1 * cr1 + sm1; m1 = mn1;
        #pragma unroll
        for (int nf = 0; nf < 8; nf++) {
            O[nf][0] *= cr0; O[nf][1] *= cr0;
            O[nf][2] *= cr1; O[nf][3] *= cr1;
        }

        // ---- O += P V  (P split hi/lo x bf16 V via ldmatrix.trans) ----
        #pragma unroll
        for (int kf = 0; kf < 4; kf++) {
            uint32_t pa[4], pl[4];
            split2(s[2*kf][0],   s[2*kf][1],   pa[0], pl[0]);
            split2(s[2*kf][2],   s[2*kf][3],   pa[1], pl[1]);
            split2(s[2*kf+1][0], s[2*kf+1][1], pa[2], pl[2]);
            split2(s[2*kf+1][2], s[2*kf+1][3], pa[3], pl[3]);
            #pragma unroll
            for (int nf = 0; nf < 8; nf++) {
                uint32_t va = st + 2 * AQ_BYTES + (kf * 16 + (lane & 15)) * AROW + nf * 16;
                uint32_t b_h[2];
                ldsm2t(b_h, va);
                mma16816(O[nf], pa, b_h);
                mma16816(O[nf], pl, b_h);
            }
        }

        __syncthreads();
        if (kt + 2 < SEQ / 64) load_kv(kt + 2, kt & 1);
        CP_COMMIT();
    }

    // ---- write ctx as split bf16 ----
    {
        float i0 = 1.0f / l0, i1 = 1.0f / l1;
        const int mr = q0 + w * 16 + (lane >> 2);
        const size_t row0 = (size_t)(b * SEQ + mr) * DMODEL;
        const size_t row1 = row0 + 8 * DMODEL;
        #pragma unroll
        for (int nf = 0; nf < 8; nf++) {
            const int n = h * HDIM + nf * 8 + (lane & 3) * 2;
            uint32_t hi, lo;
            split2(O[nf][0] * i0, O[nf][1] * i0, hi, lo);
            *(uint32_t*)(oh + row0 + n) = hi;
            *(uint32_t*)(ol + row0 + n) = lo;
            split2(O[nf][2] * i1, O[nf][3] * i1, hi, lo);
            *(uint32_t*)(oh + row1 + n) = hi;
            *(uint32_t*)(ol + row1 + n) = lo;
        }
    }
}

// ----------------------------------------------------------------------------
// LayerNorm; SPLIT=1 additionally emits bf16 hi/lo of the output
// ----------------------------------------------------------------------------
template <int SPLIT>
__global__ __launch_bounds__(256) void ln_kernel(
    const float* __restrict__ x, const float* __restrict__ g,
    const float* __restrict__ beta, float* __restrict__ y,
    __nv_bfloat16* __restrict__ yh, __nv_bfloat16* __restrict__ yl)
{
    const int row = blockIdx.x;
    const int tid = threadIdx.x;
    const float* xr = x + (size_t)row * DMODEL;

    float4 v = *(const float4*)(xr + tid * 4);
    float s  = v.x + v.y + v.z + v.w;
    float sq = v.x*v.x + v.y*v.y + v.z*v.z + v.w*v.w;

    #pragma unroll
    for (int off = 16; off > 0; off >>= 1) {
        s  += __shfl_xor_sync(0xffffffffu, s,  off);
        sq += __shfl_xor_sync(0xffffffffu, sq, off);
    }
    __shared__ float ss[8], ssq[8];
    if ((tid & 31) == 0) { ss[tid >> 5] = s; ssq[tid >> 5] = sq; }
    __syncthreads();
    float tot = 0.0f, totq = 0.0f;
    #pragma unroll
    for (int i = 0; i < 8; i++) { tot += ss[i]; totq += ssq[i]; }

    const float mu   = tot * (1.0f / DMODEL);
    const float var  = totq * (1.0f / DMODEL) - mu * mu;
    const float rstd = rsqrtf(var + 1e-5f);

    float4 gg = *(const float4*)(g + tid * 4);
    float4 bb = *(const float4*)(beta + tid * 4);
    float4 o;
    o.x = (v.x - mu) * rstd * gg.x + bb.x;
    o.y = (v.y - mu) * rstd * gg.y + bb.y;
    o.z = (v.z - mu) * rstd * gg.z + bb.z;
    o.w = (v.w - mu) * rstd * gg.w + bb.w;
    *(float4*)(y + (size_t)row * DMODEL + tid * 4) = o;

    if (SPLIT) {
        uint32_t h0, l0, h1, l1;
        split2(o.x, o.y, h0, l0);
        split2(o.z, o.w, h1, l1);
        ((uint2*)(yh + (size_t)row * DMODEL))[tid] = make_uint2(h0, h1);
        ((uint2*)(yl + (size_t)row * DMODEL))[tid] = make_uint2(l0, l1);
    }
}

// ----------------------------------------------------------------------------
// kernel_launch
// Inputs: 0 X, 1 W_qkv, 2 b_qkv, 3 W_out, 4 b_out, 5 ln1_g, 6 ln1_b,
//         7 ln2_g, 8 ln2_b, 9 W_ff1, 10 b_ff1, 11 W_ff2, 12 b_ff2
// ----------------------------------------------------------------------------
extern "C" void kernel_launch(void* const* d_in, const int* in_sizes, int n_in,
                              void* d_out, int out_size)
{
    const float* X      = (const float*)d_in[0];
    const float* W_qkv  = (const float*)d_in[1];
    const float* b_qkv  = (const float*)d_in[2];
    const float* W_out  = (const float*)d_in[3];
    const float* b_out  = (const float*)d_in[4];
    const float* ln1_g  = (const float*)d_in[5];
    const float* ln1_b  = (const float*)d_in[6];
    const float* ln2_g  = (const float*)d_in[7];
    const float* ln2_b  = (const float*)d_in[8];
    const float* W_ff1  = (const float*)d_in[9];
    const float* b_ff1  = (const float*)d_in[10];
    const float* W_ff2  = (const float*)d_in[11];
    const float* b_ff2  = (const float*)d_in[12];
    float* out = (float*)d_out;

    float *tmp, *x1;
    __nv_bfloat16 *qkh, *qkl, *ah, *al, *fh, *fl;
    __nv_bfloat16 *wqh, *wql, *woh, *wol, *w1h, *w1l, *w2h, *w2l;
    cudaGetSymbolAddress((void**)&qkh, g_qkv_h);
    cudaGetSymbolAddress((void**)&qkl, g_qkv_l);
    cudaGetSymbolAddress((void**)&tmp, g_tmp);
    cudaGetSymbolAddress((void**)&x1,  g_x1);
    cudaGetSymbolAddress((void**)&ah,  g_act_h);
    cudaGetSymbolAddress((void**)&al,  g_act_l);
    cudaGetSymbolAddress((void**)&fh,  g_ffh_h);
    cudaGetSymbolAddress((void**)&fl,  g_ffh_l);
    cudaGetSymbolAddress((void**)&wqh, g_wqkv_h);
    cudaGetSymbolAddress((void**)&wql, g_wqkv_l);
    cudaGetSymbolAddress((void**)&woh, g_wout_h);
    cudaGetSymbolAddress((void**)&wol, g_wout_l);
    cudaGetSymbolAddress((void**)&w1h, g_wff1_h);
    cudaGetSymbolAddress((void**)&w1l, g_wff1_l);
    cudaGetSymbolAddress((void**)&w2h, g_wff2_h);
    cudaGetSymbolAddress((void**)&w2l, g_wff2_l);

    cudaFuncSetAttribute(gemm_mma<0>, cudaFuncAttributeMaxDynamicSharedMemorySize, GEMM_SMEM);
    cudaFuncSetAttribute(gemm_mma<1>, cudaFuncAttributeMaxDynamicSharedMemorySize, GEMM_SMEM);
    cudaFuncSetAttribute(gemm_mma<2>, cudaFuncAttributeMaxDynamicSharedMemorySize, GEMM_SMEM);
    cudaFuncSetAttribute(gemm_mma<3>, cudaFuncAttributeMaxDynamicSharedMemorySize, GEMM_SMEM);
    cudaFuncSetAttribute(attn_mma, cudaFuncAttributeMaxDynamicSharedMemorySize, ATT_SMEM);

    dim3 tb(32, 8);
    // 0) transpose+split weights -> [N,K] bf16 hi/lo
    transpose_split_kernel<<<dim3(D3   / 32, DMODEL / 32), tb>>>(W_qkv, wqh, wql, DMODEL, D3);
    transpose_split_kernel<<<dim3(DMODEL / 32, DMODEL / 32), tb>>>(W_out, woh, wol, DMODEL, DMODEL);
    transpose_split_kernel<<<dim3(DFF  / 32, DMODEL / 32), tb>>>(W_ff1, w1h, w1l, DMODEL, DFF);
    transpose_split_kernel<<<dim3(DMODEL / 32, DFF / 32), tb>>>(W_ff2, w2h, w2l, DFF, DMODEL);

    // 1) split X; QKV projection -> split bf16 qkv
    convert_split_kernel<<<(M_ROWS * DMODEL / 4) / 256, 256>>>(X, ah, al, M_ROWS * DMODEL / 4);
    gemm_mma<3><<<dim3(D3 / BN, M_ROWS / BM), 256, GEMM_SMEM>>>(
        ah, al, wqh, wql, b_qkv, nullptr, nullptr, qkh, qkl, D3, DMODEL);

    // 2) tensor-core attention -> ctx split bf16 (reuses act buffers)
    attn_mma<<<dim3(SEQ / 64, 8 * NHEAD), 128, ATT_SMEM>>>(qkh, qkl, ah, al);

    // 3) out-proj + residual(X) -> tmp fp32
    gemm_mma<1><<<dim3(DMODEL / BN, M_ROWS / BM), 256, GEMM_SMEM>>>(
        ah, al, woh, wol, b_out, X, tmp, nullptr, nullptr, DMODEL, DMODEL);

    // 4) LN1 -> x1 fp32 + split (act buffers)
    ln_kernel<1><<<M_ROWS, 256>>>(tmp, ln1_g, ln1_b, x1, ah, al);

    // 5) FF1 + GELU -> split bf16
    gemm_mma<2><<<dim3(DFF / BN, M_ROWS / BM), 256, GEMM_SMEM>>>(
        ah, al, w1h, w1l, b_ff1, nullptr, nullptr, fh, fl, DFF, DMODEL);

    // 6) FF2 + residual(x1) -> tmp fp32
    gemm_mma<1><<<dim3(DMODEL / BN, M_ROWS / BM), 256, GEMM_SMEM>>>(
        fh, fl, w2h, w2l, b_ff2, x1, tmp, nullptr, nullptr, DMODEL, DFF);

    // 7) LN2 -> out
    ln_kernel<0><<<M_ROWS, 256>>>(tmp, ln2_g, ln2_b, out, nullptr, nullptr);
}

// round 12
// speedup vs baseline: 1.5085x; 1.5085x over previous
#include <cuda_runtime.h>
#include <cuda_fp16.h>
#include <math.h>
#include <stdint.h>

// ----------------------------------------------------------------------------
// Problem constants: B=8, T=1024, D=1024, H=16, HD=64.  M = B*T = 8192.
// ----------------------------------------------------------------------------
#define M_ROWS 8192
#define DMODEL 1024
#define D3     3072
#define DFF    4096
#define NHEAD  16
#define HDIM   64
#define SEQ    1024

// ----------------------------------------------------------------------------
// Scratch (device globals -- no cudaMalloc allowed)
// fp16x2 emulation: x ~= hi + lo, |lo| <= 2^-11 |x|.
// GEMM uses 2 MMAs: (Ah+Al) x Bh  (B lo dropped, err ~1.4e-4 RMS).
// ----------------------------------------------------------------------------
__device__ __half g_qkv_h[M_ROWS * D3];       // QKV hi
__device__ __half g_qkv_l[M_ROWS * D3];       // QKV lo (only Q part consumed)
__device__ float g_tmp[M_ROWS * DMODEL];      // fp32 pre-LN buffers
__device__ float g_x1 [M_ROWS * DMODEL];
__device__ __half g_act_h[M_ROWS * DMODEL];   // activation hi (X / ctx / x1)
__device__ __half g_act_l[M_ROWS * DMODEL];   // activation lo
__device__ __half g_ffh_h[M_ROWS * DFF];      // FF1 out hi
__device__ __half g_ffh_l[M_ROWS * DFF];      // FF1 out lo
// weights, transposed to [N,K], fp16 hi only
__device__ __half g_wqkv_h[DMODEL * D3];
__device__ __half g_wout_h[DMODEL * DMODEL];
__device__ __half g_wff1_h[DMODEL * DFF];
__device__ __half g_wff2_h[DFF * DMODEL];

// ----------------------------------------------------------------------------
// PTX helpers (compute_103-baseline legal: cp.async / ldmatrix / mma.sync)
// ----------------------------------------------------------------------------
__device__ __forceinline__ uint32_t smem_to_u32(const void* smem_ptr) {
    uint32_t addr;
    asm("{ .reg .u64 tmp; cvta.to.shared.u64 tmp, %1; cvt.u32.u64 %0, tmp; }"
        : "=r"(addr) : "l"(smem_ptr));
    return addr;
}

__device__ __forceinline__ void cp16(uint32_t smem_addr, const void* gptr) {
    asm volatile("cp.async.cg.shared.global [%0], [%1], 16;"
                 :: "r"(smem_addr), "l"(gptr));
}
#define CP_COMMIT() asm volatile("cp.async.commit_group;" ::: "memory")
#define CP_WAIT1()  asm volatile("cp.async.wait_group 1;" ::: "memory")

__device__ __forceinline__ void ldsm4(uint32_t* d, uint32_t addr) {
    asm volatile("ldmatrix.sync.aligned.m8n8.x4.shared.b16 {%0,%1,%2,%3}, [%4];"
        : "=r"(d[0]), "=r"(d[1]), "=r"(d[2]), "=r"(d[3]) : "r"(addr));
}
__device__ __forceinline__ void ldsm2(uint32_t* d, uint32_t addr) {
    asm volatile("ldmatrix.sync.aligned.m8n8.x2.shared.b16 {%0,%1}, [%2];"
        : "=r"(d[0]), "=r"(d[1]) : "r"(addr));
}
__device__ __forceinline__ void ldsm2t(uint32_t* d, uint32_t addr) {
    asm volatile("ldmatrix.sync.aligned.m8n8.x2.trans.shared.b16 {%0,%1}, [%2];"
        : "=r"(d[0]), "=r"(d[1]) : "r"(addr));
}

__device__ __forceinline__ void mma16816(float* c, const uint32_t* a, const uint32_t* b) {
    asm volatile("mma.sync.aligned.m16n8k16.row.col.f32.f16.f16.f32 "
        "{%0,%1,%2,%3}, {%4,%5,%6,%7}, {%8,%9}, {%0,%1,%2,%3};"
        : "+f"(c[0]), "+f"(c[1]), "+f"(c[2]), "+f"(c[3])
        : "r"(a[0]), "r"(a[1]), "r"(a[2]), "r"(a[3]), "r"(b[0]), "r"(b[1]));
}

// ----------------------------------------------------------------------------
// Split: fp32 -> (fp16 hi, fp16 lo) so x ~= hi + lo
// ----------------------------------------------------------------------------
__device__ __forceinline__ void split2(float a, float b, uint32_t& h, uint32_t& l) {
    __half ha = __float2half(a);
    __half hb = __float2half(b);
    __half la = __float2half(a - __half2float(ha));
    __half lb = __float2half(b - __half2float(hb));
    __half2 hp(ha, hb), lp(la, lb);
    h = *(uint32_t*)&hp; l = *(uint32_t*)&lp;
}

__global__ __launch_bounds__(256) void convert_split_kernel(
    const float* __restrict__ x, __half* __restrict__ h,
    __half* __restrict__ l, int n4)
{
    int i = blockIdx.x * 256 + threadIdx.x;
    if (i >= n4) return;
    float4 v = ((const float4*)x)[i];
    uint32_t h0, l0, h1, l1;
    split2(v.x, v.y, h0, l0);
    split2(v.z, v.w, h1, l1);
    ((uint2*)h)[i] = make_uint2(h0, h1);
    ((uint2*)l)[i] = make_uint2(l0, l1);
}

// W [K,N] fp32 row-major -> Wt [N,K] fp16 (32x32 tiles), hi only
__global__ __launch_bounds__(256) void transpose_h_kernel(
    const float* __restrict__ W, __half* __restrict__ h, int K, int N)
{
    __shared__ float t[32][33];
    const int tx = threadIdx.x;
    const int ty = threadIdx.y;
    const int k0 = blockIdx.y * 32;
    const int n0 = blockIdx.x * 32;
    #pragma unroll
    for (int r = 0; r < 4; r++)
        t[ty * 4 + r][tx] = W[(size_t)(k0 + ty * 4 + r) * N + n0 + tx];
    __syncthreads();
    #pragma unroll
    for (int r = 0; r < 4; r++) {
        int n = n0 + ty * 4 + r;
        h[(size_t)n * K + k0 + tx] = __float2half(t[tx][ty * 4 + r]);
    }
}

// ----------------------------------------------------------------------------
// mma.sync fp16x2 GEMM:  C[M,N] = A[M,K] @ Bt[N,K]^T + bias (+ epilogue)
//   A ~ Ah + Al (fp16 [M,K]);  B ~ Bh (fp16 [N,K], lo dropped).
//   A*B ~= Ah*Bh + Al*Bh  (fp32 accumulation), err ~1.4e-4 RMS.
// Tile: 128x128, BK=32, 256 threads (8 warps, each 64x32), 3-stage cp.async.
// EPI: 0 = bias -> fp32;  1 = bias + residual -> fp32;
//      2 = bias + exact GELU -> split fp16;  3 = bias -> split fp16
// ----------------------------------------------------------------------------
#define BM 128
#define BN 128
#define BK 32
#define ROWB 80
#define AH_OFF 0
#define AL_OFF 10240
#define BH_OFF 20480
#define STAGE_BYTES 30720
#define GEMM_SMEM (3 * STAGE_BYTES)   // 92160

__device__ __forceinline__ float gelu_exact(float x) {
    return 0.5f * x * (1.0f + erff(x * 0.70710678118654752440f));
}

template <int EPI>
__global__ __launch_bounds__(256) void gemm_mma(
    const __half* __restrict__ Ah, const __half* __restrict__ Al,
    const __half* __restrict__ Bh,
    const float* __restrict__ bias, const float* __restrict__ res,
    float* __restrict__ C, __half* __restrict__ Ch,
    __half* __restrict__ Cl, int N, int K)
{
    extern __shared__ char smem[];
    const uint32_t sbase = smem_to_u32(smem);
    const int tid  = threadIdx.x;
    const int wid  = tid >> 5;
    const int lane = tid & 31;
    const int m0 = blockIdx.y * BM;
    const int n0 = blockIdx.x * BN;

    const int r  = tid >> 1;
    const int c2 = (tid & 1) * 2;

    const int wm = (wid & 1) * 64;
    const int wn = (wid >> 1) * 32;

    float acc[4][4][4];
    #pragma unroll
    for (int i = 0; i < 4; i++)
        #pragma unroll
        for (int j = 0; j < 4; j++)
            #pragma unroll
            for (int k = 0; k < 4; k++) acc[i][j][k] = 0.0f;

    const int KT = K / BK;

    auto load_stage = [&](int it, int s) {
        const int kc = it * BK;
        const uint32_t st = sbase + s * STAGE_BYTES;
        const uint32_t sa = st + r * ROWB + c2 * 16;
        const size_t ga = (size_t)(m0 + r) * K + kc + c2 * 8;
        const size_t gb = (size_t)(n0 + r) * K + kc + c2 * 8;
        cp16(sa + AH_OFF,      Ah + ga);
        cp16(sa + AH_OFF + 16, Ah + ga + 8);
        cp16(sa + AL_OFF,      Al + ga);
        cp16(sa + AL_OFF + 16, Al + ga + 8);
        cp16(sa + BH_OFF,      Bh + gb);
        cp16(sa + BH_OFF + 16, Bh + gb + 8);
    };

    load_stage(0, 0); CP_COMMIT();
    load_stage(1, 1); CP_COMMIT();

    for (int it = 0; it < KT; it++) {
        CP_WAIT1();
        __syncthreads();
        const int nx = it + 2;
        if (nx < KT) load_stage(nx, nx % 3);
        CP_COMMIT();

        const uint32_t st = sbase + (it % 3) * STAGE_BYTES;
        #pragma unroll
        for (int ks = 0; ks < 2; ks++) {
            const int kb  = (ks * 16 + (lane >> 4) * 8) * 2;
            const int kbB = (ks * 16 + ((lane >> 3) & 1) * 8) * 2;
            uint32_t a_h[4][4], a_l[4][4], b_h[4][2];
            #pragma unroll
            for (int mf = 0; mf < 4; mf++) {
                uint32_t ra = st + (wm + mf * 16 + (lane & 15)) * ROWB + kb;
                ldsm4(a_h[mf], ra + AH_OFF);
                ldsm4(a_l[mf], ra + AL_OFF);
            }
            #pragma unroll
            for (int nf = 0; nf < 4; nf++) {
                uint32_t rb = st + (wn + nf * 8 + (lane & 7)) * ROWB + kbB;
                ldsm2(b_h[nf], rb + BH_OFF);
            }
            #pragma unroll
            for (int mf = 0; mf < 4; mf++)
                #pragma unroll
                for (int nf = 0; nf < 4; nf++) {
                    mma16816(acc[mf][nf], a_h[mf], b_h[nf]);
                    mma16816(acc[mf][nf], a_l[mf], b_h[nf]);
                }
        }
    }

    #pragma unroll
    for (int mf = 0; mf < 4; mf++) {
        const int m = m0 + wm + mf * 16 + (lane >> 2);
        #pragma unroll
        for (int nf = 0; nf < 4; nf++) {
            const int n = n0 + wn + nf * 8 + (lane & 3) * 2;
            float2 bv = *(const float2*)(bias + n);
            float* a = acc[mf][nf];
            float v0 = a[0] + bv.x, v1 = a[1] + bv.y;
            float v2 = a[2] + bv.x, v3 = a[3] + bv.y;
            if (EPI == 1) {
                float2 r0 = *(const float2*)(res + (size_t)m * N + n);
                float2 r1 = *(const float2*)(res + (size_t)(m + 8) * N + n);
                v0 += r0.x; v1 += r0.y; v2 += r1.x; v3 += r1.y;
            }
            if (EPI == 2) {
                v0 = gelu_exact(v0); v1 = gelu_exact(v1);
                v2 = gelu_exact(v2); v3 = gelu_exact(v3);
            }
            if (EPI >= 2) {
                uint32_t h0, l0, h1, l1;
                split2(v0, v1, h0, l0);
                split2(v2, v3, h1, l1);
                *(uint32_t*)(Ch + (size_t)m * N + n)       = h0;
                *(uint32_t*)(Cl + (size_t)m * N + n)       = l0;
                *(uint32_t*)(Ch + (size_t)(m + 8) * N + n) = h1;
                *(uint32_t*)(Cl + (size_t)(m + 8) * N + n) = l1;
            } else {
                *(float2*)(C + (size_t)m * N + n)       = make_float2(v0, v1);
                *(float2*)(C + (size_t)(m + 8) * N + n) = make_float2(v2, v3);
            }
        }
    }
}

// ----------------------------------------------------------------------------
// Tensor-core flash attention (fp16x2).
// CTA: 64 q rows x one (b,h); 4 warps x 16 q rows; K tiles of 64 keys.
// S = (Qh+Ql)*Kh  (K lo dropped);  softmax in mma layout;
// O += (Ph+Pl)*Vh (P exact to 2^-22, V lo dropped).
// Emits ctx directly as split fp16 (oh, ol).
// ----------------------------------------------------------------------------
#define AROW 144                       // smem row stride bytes (64 halves + pad)
#define AQ_BYTES (64 * AROW)           // 9216 per 64x64 tile
#define AST (2 * AQ_BYTES)             // stage: Kh,Vh = 18432
#define ATT_SMEM (2 * AQ_BYTES + 2 * AST)  // 55296

__global__ __launch_bounds__(128) void attn_mma(
    const __half* __restrict__ qh, const __half* __restrict__ ql,
    __half* __restrict__ oh, __half* __restrict__ ol)
{
    extern __shared__ char smem[];
    const uint32_t sb = smem_to_u32(smem);
    const int tid  = threadIdx.x;
    const int w    = tid >> 5;
    const int lane = tid & 31;
    const int bh = blockIdx.y;
    const int b  = bh >> 4;
    const int h  = bh & 15;
    const int q0 = blockIdx.x * 64;

    const uint32_t QHs = sb;
    const uint32_t QLs = sb + AQ_BYTES;

    const int r  = tid >> 1;           // 0..63
    const int cb = (tid & 1) * 4;      // chunk base (16B chunks)

    {
        const size_t g = (size_t)(b * SEQ + q0 + r) * D3 + h * HDIM + cb * 8;
        const uint32_t o = r * AROW + cb * 16;
        #pragma unroll
        for (int c = 0; c < 4; c++) {
            cp16(QHs + o + c * 16, qh + g + c * 8);
            cp16(QLs + o + c * 16, ql + g + c * 8);
        }
    }
    auto load_kv = [&](int kt, int s) {
        const uint32_t st = sb + 2 * AQ_BYTES + s * AST;
        const size_t gk = (size_t)(b * SEQ + kt * 64 + r) * D3 + DMODEL + h * HDIM + cb * 8;
        const size_t gv = gk + DMODEL;
        const uint32_t o = r * AROW + cb * 16;
        #pragma unroll
        for (int c = 0; c < 4; c++) {
            cp16(st + o + c * 16,            qh + gk + c * 8);
            cp16(st + AQ_BYTES + o + c * 16, qh + gv + c * 8);
        }
    };
    load_kv(0, 0); CP_COMMIT();
    load_kv(1, 1); CP_COMMIT();

    uint32_t qfh[4][4], qfl[4][4];
    float O[8][4];
    #pragma unroll
    for (int i = 0; i < 8; i++)
        #pragma unroll
        for (int j = 0; j < 4; j++) O[i][j] = 0.0f;
    float m0 = -1e30f, m1 = -1e30f, l0 = 0.0f, l1 = 0.0f;

    for (int kt = 0; kt < SEQ / 64; kt++) {
        CP_WAIT1();
        __syncthreads();
        if (kt == 0) {
            #pragma unroll
            for (int kf = 0; kf < 4; kf++) {
                uint32_t qa = QHs + (w * 16 + (lane & 15)) * AROW + kf * 32 + (lane >> 4) * 16;
                ldsm4(qfh[kf], qa);
                ldsm4(qfl[kf], qa + AQ_BYTES);
            }
        }
        const uint32_t st = sb + 2 * AQ_BYTES + (kt & 1) * AST;

        // ---- S = Q K^T  (warp: 16q x 64k) ----
        float s[8][4];
        #pragma unroll
        for (int i = 0; i < 8; i++)
            #pragma unroll
            for (int j = 0; j < 4; j++) s[i][j] = 0.0f;
        #pragma unroll
        for (int kf = 0; kf < 4; kf++) {
            #pragma unroll
            for (int nf = 0; nf < 8; nf++) {
                uint32_t ka = st + (nf * 8 + (lane & 7)) * AROW + kf * 32 + ((lane >> 3) & 1) * 16;
                uint32_t b_h[2];
                ldsm2(b_h, ka);
                mma16816(s[nf], qfh[kf], b_h);
                mma16816(s[nf], qfl[kf], b_h);
            }
        }

        // ---- online softmax in mma layout ----
        float mx0 = -1e30f, mx1 = -1e30f;
        #pragma unroll
        for (int nf = 0; nf < 8; nf++) {
            s[nf][0] *= 0.125f; s[nf][1] *= 0.125f;
            s[nf][2] *= 0.125f; s[nf][3] *= 0.125f;
            mx0 = fmaxf(mx0, fmaxf(s[nf][0], s[nf][1]));
            mx1 = fmaxf(mx1, fmaxf(s[nf][2], s[nf][3]));
        }
        mx0 = fmaxf(mx0, __shfl_xor_sync(0xffffffffu, mx0, 1));
        mx0 = fmaxf(mx0, __shfl_xor_sync(0xffffffffu, mx0, 2));
        mx1 = fmaxf(mx1, __shfl_xor_sync(0xffffffffu, mx1, 1));
        mx1 = fmaxf(mx1, __shfl_xor_sync(0xffffffffu, mx1, 2));
        float mn0 = fmaxf(m0, mx0), mn1 = fmaxf(m1, mx1);
        float cr0 = __expf(m0 - mn0), cr1 = __expf(m1 - mn1);
        float sm0 = 0.0f, sm1 = 0.0f;
        #pragma unroll
        for (int nf = 0; nf < 8; nf++) {
            s[nf][0] = __expf(s[nf][0] - mn0); sm0 += s[nf][0];
            s[nf][1] = __expf(s[nf][1] - mn0); sm0 += s[nf][1];
            s[nf][2] = __expf(s[nf][2] - mn1); sm1 += s[nf][2];
            s[nf][3] = __expf(s[nf][3] - mn1); sm1 += s[nf][3];
        }
        sm0 += __shfl_xor_sync(0xffffffffu, sm0, 1);
        sm0 += __shfl_xor_sync(0xffffffffu, sm0, 2);
        sm1 += __shfl_xor_sync(0xffffffffu, sm1, 1);
        sm1 += __shfl_xor_sync(0xffffffffu, sm1, 2);
        l0 = l0 * cr0 + sm0; m0 = mn0;
        l1 = l1 * cr1 + sm1; m1 = mn1;
        #pragma unroll
        for (int nf = 0; nf < 8; nf++) {
            O[nf][0] *= cr0; O[nf][1] *= cr0;
            O[nf][2] *= cr1; O[nf][3] *= cr1;
        }

        // ---- O += P V  (P split hi/lo x fp16 V via ldmatrix.trans) ----
        #pragma unroll
        for (int kf = 0; kf < 4; kf++) {
            uint32_t pa[4], pl[4];
            split2(s[2*kf][0],   s[2*kf][1],   pa[0], pl[0]);
            split2(s[2*kf][2],   s[2*kf][3],   pa[1], pl[1]);
            split2(s[2*kf+1][0], s[2*kf+1][1], pa[2], pl[2]);
            split2(s[2*kf+1][2], s[2*kf+1][3], pa[3], pl[3]);
            #pragma unroll
            for (int nf = 0; nf < 8; nf++) {
                uint32_t va = st + AQ_BYTES + (kf * 16 + (lane & 15)) * AROW + nf * 16;
                uint32_t b_h[2];
                ldsm2t(b_h, va);
                mma16816(O[nf], pa, b_h);
                mma16816(O[nf], pl, b_h);
            }
        }

        __syncthreads();
        if (kt + 2 < SEQ / 64) load_kv(kt + 2, kt & 1);
        CP_COMMIT();
    }

    // ---- write ctx as split fp16 ----
    {
        float i0 = 1.0f / l0, i1 = 1.0f / l1;
        const int mr = q0 + w * 16 + (lane >> 2);
        const size_t row0 = (size_t)(b * SEQ + mr) * DMODEL;
        const size_t row1 = row0 + 8 * DMODEL;
        #pragma unroll
        for (int nf = 0; nf < 8; nf++) {
            const int n = h * HDIM + nf * 8 + (lane & 3) * 2;
            uint32_t hi, lo;
            split2(O[nf][0] * i0, O[nf][1] * i0, hi, lo);
            *(uint32_t*)(oh + row0 + n) = hi;
            *(uint32_t*)(ol + row0 + n) = lo;
            split2(O[nf][2] * i1, O[nf][3] * i1, hi, lo);
            *(uint32_t*)(oh + row1 + n) = hi;
            *(uint32_t*)(ol + row1 + n) = lo;
        }
    }
}

// ----------------------------------------------------------------------------
// LayerNorm; SPLIT=1 additionally emits fp16 hi/lo of the output
// ----------------------------------------------------------------------------
template <int SPLIT>
__global__ __launch_bounds__(256) void ln_kernel(
    const float* __restrict__ x, const float* __restrict__ g,
    const float* __restrict__ beta, float* __restrict__ y,
    __half* __restrict__ yh, __half* __restrict__ yl)
{
    const int row = blockIdx.x;
    const int tid = threadIdx.x;
    const float* xr = x + (size_t)row * DMODEL;

    float4 v = *(const float4*)(xr + tid * 4);
    float s  = v.x + v.y + v.z + v.w;
    float sq = v.x*v.x + v.y*v.y + v.z*v.z + v.w*v.w;

    #pragma unroll
    for (int off = 16; off > 0; off >>= 1) {
        s  += __shfl_xor_sync(0xffffffffu, s,  off);
        sq += __shfl_xor_sync(0xffffffffu, sq, off);
    }
    __shared__ float ss[8], ssq[8];
    if ((tid & 31) == 0) { ss[tid >> 5] = s; ssq[tid >> 5] = sq; }
    __syncthreads();
    float tot = 0.0f, totq = 0.0f;
    #pragma unroll
    for (int i = 0; i < 8; i++) { tot += ss[i]; totq += ssq[i]; }

    const float mu   = tot * (1.0f / DMODEL);
    const float var  = totq * (1.0f / DMODEL) - mu * mu;
    const float rstd = rsqrtf(var + 1e-5f);

    float4 gg = *(const float4*)(g + tid * 4);
    float4 bb = *(const float4*)(beta + tid * 4);
    float4 o;
    o.x = (v.x - mu) * rstd * gg.x + bb.x;
    o.y = (v.y - mu) * rstd * gg.y + bb.y;
    o.z = (v.z - mu) * rstd * gg.z + bb.z;
    o.w = (v.w - mu) * rstd * gg.w + bb.w;
    *(float4*)(y + (size_t)row * DMODEL + tid * 4) = o;

    if (SPLIT) {
        uint32_t h0, l0, h1, l1;
        split2(o.x, o.y, h0, l0);
        split2(o.z, o.w, h1, l1);
        ((uint2*)(yh + (size_t)row * DMODEL))[tid] = make_uint2(h0, h1);
        ((uint2*)(yl + (size_t)row * DMODEL))[tid] = make_uint2(l0, l1);
    }
}

// ----------------------------------------------------------------------------
// kernel_launch
// Inputs: 0 X, 1 W_qkv, 2 b_qkv, 3 W_out, 4 b_out, 5 ln1_g, 6 ln1_b,
//         7 ln2_g, 8 ln2_b, 9 W_ff1, 10 b_ff1, 11 W_ff2, 12 b_ff2
// ----------------------------------------------------------------------------
extern "C" void kernel_launch(void* const* d_in, const int* in_sizes, int n_in,
                              void* d_out, int out_size)
{
    const float* X      = (const float*)d_in[0];
    const float* W_qkv  = (const float*)d_in[1];
    const float* b_qkv  = (const float*)d_in[2];
    const float* W_out  = (const float*)d_in[3];
    const float* b_out  = (const float*)d_in[4];
    const float* ln1_g  = (const float*)d_in[5];
    const float* ln1_b  = (const float*)d_in[6];
    const float* ln2_g  = (const float*)d_in[7];
    const float* ln2_b  = (const float*)d_in[8];
    const float* W_ff1  = (const float*)d_in[9];
    const float* b_ff1  = (const float*)d_in[10];
    const float* W_ff2  = (const float*)d_in[11];
    const float* b_ff2  = (const float*)d_in[12];
    float* out = (float*)d_out;

    float *tmp, *x1;
    __half *qkh, *qkl, *ah, *al, *fh, *fl;
    __half *wqh, *woh, *w1h, *w2h;
    cudaGetSymbolAddress((void**)&qkh, g_qkv_h);
    cudaGetSymbolAddress((void**)&qkl, g_qkv_l);
    cudaGetSymbolAddress((void**)&tmp, g_tmp);
    cudaGetSymbolAddress((void**)&x1,  g_x1);
    cudaGetSymbolAddress((void**)&ah,  g_act_h);
    cudaGetSymbolAddress((void**)&al,  g_act_l);
    cudaGetSymbolAddress((void**)&fh,  g_ffh_h);
    cudaGetSymbolAddress((void**)&fl,  g_ffh_l);
    cudaGetSymbolAddress((void**)&wqh, g_wqkv_h);
    cudaGetSymbolAddress((void**)&woh, g_wout_h);
    cudaGetSymbolAddress((void**)&w1h, g_wff1_h);
    cudaGetSymbolAddress((void**)&w2h, g_wff2_h);

    cudaFuncSetAttribute(gemm_mma<0>, cudaFuncAttributeMaxDynamicSharedMemorySize, GEMM_SMEM);
    cudaFuncSetAttribute(gemm_mma<1>, cudaFuncAttributeMaxDynamicSharedMemorySize, GEMM_SMEM);
    cudaFuncSetAttribute(gemm_mma<2>, cudaFuncAttributeMaxDynamicSharedMemorySize, GEMM_SMEM);
    cudaFuncSetAttribute(gemm_mma<3>, cudaFuncAttributeMaxDynamicSharedMemorySize, GEMM_SMEM);
    cudaFuncSetAttribute(attn_mma, cudaFuncAttributeMaxDynamicSharedMemorySize, ATT_SMEM);

    dim3 tb(32, 8);
    // 0) transpose weights -> [N,K] fp16 hi
    transpose_h_kernel<<<dim3(D3   / 32, DMODEL / 32), tb>>>(W_qkv, wqh, DMODEL, D3);
    transpose_h_kernel<<<dim3(DMODEL / 32, DMODEL / 32), tb>>>(W_out, woh, DMODEL, DMODEL);
    transpose_h_kernel<<<dim3(DFF  / 32, DMODEL / 32), tb>>>(W_ff1, w1h, DMODEL, DFF);
    transpose_h_kernel<<<dim3(DMODEL / 32, DFF / 32), tb>>>(W_ff2, w2h, DFF, DMODEL);

    // 1) split X; QKV projection -> split fp16 qkv
    convert_split_kernel<<<(M_ROWS * DMODEL / 4) / 256, 256>>>(X, ah, al, M_ROWS * DMODEL / 4);
    gemm_mma<3><<<dim3(D3 / BN, M_ROWS / BM), 256, GEMM_SMEM>>>(
        ah, al, wqh, b_qkv, nullptr, nullptr, qkh, qkl, D3, DMODEL);

    // 2) tensor-core attention -> ctx split fp16 (reuses act buffers)
    attn_mma<<<dim3(SEQ / 64, 8 * NHEAD), 128, ATT_SMEM>>>(qkh, qkl, ah, al);

    // 3) out-proj + residual(X) -> tmp fp32
    gemm_mma<1><<<dim3(DMODEL / BN, M_ROWS / BM), 256, GEMM_SMEM>>>(
        ah, al, woh, b_out, X, tmp, nullptr, nullptr, DMODEL, DMODEL);

    // 4) LN1 -> x1 fp32 + split (act buffers)
    ln_kernel<1><<<M_ROWS, 256>>>(tmp, ln1_g, ln1_b, x1, ah, al);

    // 5) FF1 + GELU -> split fp16
    gemm_mma<2><<<dim3(DFF / BN, M_ROWS / BM), 256, GEMM_SMEM>>>(
        ah, al, w1h, b_ff1, nullptr, nullptr, fh, fl, DFF, DMODEL);

    // 6) FF2 + residual(x1) -> tmp fp32
    gemm_mma<1><<<dim3(DMODEL / BN, M_ROWS / BM), 256, GEMM_SMEM>>>(
        fh, fl, w2h, b_ff2, x1, tmp, nullptr, nullptr, DMODEL, DFF);

    // 7) LN2 -> out
    ln_kernel<0><<<M_ROWS, 256>>>(tmp, ln2_g, ln2_b, out, nullptr, nullptr);
}

// round 13
// speedup vs baseline: 2.0068x; 1.3303x over previous
#include <cuda_runtime.h>
#include <cuda_fp16.h>
#include <math.h>
#include <stdint.h>

// ----------------------------------------------------------------------------
// Problem constants: B=8, T=1024, D=1024, H=16, HD=64.  M = B*T = 8192.
// ----------------------------------------------------------------------------
#define M_ROWS 8192
#define DMODEL 1024
#define D3     3072
#define DFF    4096
#define NHEAD  16
#define HDIM   64
#define SEQ    1024

// ----------------------------------------------------------------------------
// Scratch (device globals -- no cudaMalloc allowed)
// Pure-fp16 GEMMs (1 MMA/product). Attention keeps hi+lo Q and P correction.
// ----------------------------------------------------------------------------
__device__ __half g_qkv_h[M_ROWS * D3];       // QKV hi
__device__ __half g_qkv_l[M_ROWS * D3];       // QKV lo (only Q part consumed)
__device__ float g_tmp[M_ROWS * DMODEL];      // fp32 pre-LN buffers
__device__ float g_x1 [M_ROWS * DMODEL];
__device__ __half g_act_h[M_ROWS * DMODEL];   // activation hi (X / ctx / x1)
__device__ __half g_ffh_h[M_ROWS * DFF];      // FF1 out hi
// weights, transposed to [N,K], fp16
__device__ __half g_wqkv_h[DMODEL * D3];
__device__ __half g_wout_h[DMODEL * DMODEL];
__device__ __half g_wff1_h[DMODEL * DFF];
__device__ __half g_wff2_h[DFF * DMODEL];

// ----------------------------------------------------------------------------
// PTX helpers (compute_103-baseline legal: cp.async / ldmatrix / mma.sync)
// ----------------------------------------------------------------------------
__device__ __forceinline__ uint32_t smem_to_u32(const void* smem_ptr) {
    uint32_t addr;
    asm("{ .reg .u64 tmp; cvta.to.shared.u64 tmp, %1; cvt.u32.u64 %0, tmp; }"
        : "=r"(addr) : "l"(smem_ptr));
    return addr;
}

__device__ __forceinline__ void cp16(uint32_t smem_addr, const void* gptr) {
    asm volatile("cp.async.cg.shared.global [%0], [%1], 16;"
                 :: "r"(smem_addr), "l"(gptr));
}
#define CP_COMMIT() asm volatile("cp.async.commit_group;" ::: "memory")
#define CP_WAIT1()  asm volatile("cp.async.wait_group 1;" ::: "memory")

__device__ __forceinline__ void ldsm4(uint32_t* d, uint32_t addr) {
    asm volatile("ldmatrix.sync.aligned.m8n8.x4.shared.b16 {%0,%1,%2,%3}, [%4];"
        : "=r"(d[0]), "=r"(d[1]), "=r"(d[2]), "=r"(d[3]) : "r"(addr));
}
__device__ __forceinline__ void ldsm2(uint32_t* d, uint32_t addr) {
    asm volatile("ldmatrix.sync.aligned.m8n8.x2.shared.b16 {%0,%1}, [%2];"
        : "=r"(d[0]), "=r"(d[1]) : "r"(addr));
}
__device__ __forceinline__ void ldsm2t(uint32_t* d, uint32_t addr) {
    asm volatile("ldmatrix.sync.aligned.m8n8.x2.trans.shared.b16 {%0,%1}, [%2];"
        : "=r"(d[0]), "=r"(d[1]) : "r"(addr));
}

__device__ __forceinline__ void mma16816(float* c, const uint32_t* a, const uint32_t* b) {
    asm volatile("mma.sync.aligned.m16n8k16.row.col.f32.f16.f16.f32 "
        "{%0,%1,%2,%3}, {%4,%5,%6,%7}, {%8,%9}, {%0,%1,%2,%3};"
        : "+f"(c[0]), "+f"(c[1]), "+f"(c[2]), "+f"(c[3])
        : "r"(a[0]), "r"(a[1]), "r"(a[2]), "r"(a[3]), "r"(b[0]), "r"(b[1]));
}

// ----------------------------------------------------------------------------
// Split: fp32 -> (fp16 hi, fp16 lo) so x ~= hi + lo
// ----------------------------------------------------------------------------
__device__ __forceinline__ void split2(float a, float b, uint32_t& h, uint32_t& l) {
    __half ha = __float2half(a);
    __half hb = __float2half(b);
    __half la = __float2half(a - __half2float(ha));
    __half lb = __float2half(b - __half2float(hb));
    __half2 hp(ha, hb), lp(la, lb);
    h = *(uint32_t*)&hp; l = *(uint32_t*)&lp;
}
__device__ __forceinline__ uint32_t pack2h(float a, float b) {
    __half2 hp(__float2half(a), __float2half(b));
    return *(uint32_t*)&hp;
}

__global__ __launch_bounds__(256) void convert_h_kernel(
    const float* __restrict__ x, __half* __restrict__ h, int n4)
{
    int i = blockIdx.x * 256 + threadIdx.x;
    if (i >= n4) return;
    float4 v = ((const float4*)x)[i];
    ((uint2*)h)[i] = make_uint2(pack2h(v.x, v.y), pack2h(v.z, v.w));
}

// W [K,N] fp32 row-major -> Wt [N,K] fp16 (32x32 tiles)
__global__ __launch_bounds__(256) void transpose_h_kernel(
    const float* __restrict__ W, __half* __restrict__ h, int K, int N)
{
    __shared__ float t[32][33];
    const int tx = threadIdx.x;
    const int ty = threadIdx.y;
    const int k0 = blockIdx.y * 32;
    const int n0 = blockIdx.x * 32;
    #pragma unroll
    for (int r = 0; r < 4; r++)
        t[ty * 4 + r][tx] = W[(size_t)(k0 + ty * 4 + r) * N + n0 + tx];
    __syncthreads();
    #pragma unroll
    for (int r = 0; r < 4; r++) {
        int n = n0 + ty * 4 + r;
        h[(size_t)n * K + k0 + tx] = __float2half(t[tx][ty * 4 + r]);
    }
}

// ----------------------------------------------------------------------------
// Pure-fp16 mma.sync GEMM:  C[M,N] = A[M,K] @ Bt[N,K]^T + bias (+ epilogue)
// 1 MMA per product; fp32 accumulate.  Tile 128x256, BK=32, 256 threads
// (8 warps, 2x4 grid, each 64x64), 3-stage cp.async.
// EPI: 0 = bias -> fp32;  1 = bias + residual -> fp32;
//      2 = bias + exact GELU -> fp16 hi;  3 = bias -> fp16 hi + lo
// ----------------------------------------------------------------------------
#define BM 128
#define BN 256
#define BK 32
#define ROWB 80
#define AH_OFF 0
#define BH_OFF 10240
#define STAGE_BYTES 30720
#define GEMM_SMEM (3 * STAGE_BYTES)   // 92160

__device__ __forceinline__ float gelu_exact(float x) {
    return 0.5f * x * (1.0f + erff(x * 0.70710678118654752440f));
}

template <int EPI>
__global__ __launch_bounds__(256) void gemm_mma(
    const __half* __restrict__ Ah, const __half* __restrict__ Bh,
    const float* __restrict__ bias, const float* __restrict__ res,
    float* __restrict__ C, __half* __restrict__ Ch,
    __half* __restrict__ Cl, int N, int K)
{
    extern __shared__ char smem[];
    const uint32_t sbase = smem_to_u32(smem);
    const int tid  = threadIdx.x;
    const int wid  = tid >> 5;
    const int lane = tid & 31;
    const int m0 = blockIdx.y * BM;
    const int n0 = blockIdx.x * BN;

    // A loader: 2 threads/row, 2 chunks each; B loader: 1 thread/row, 4 chunks
    const int rA = tid >> 1;
    const int cA = (tid & 1) * 2;

    // warp tile 64x64
    const int wm = (wid & 1) * 64;
    const int wn = (wid >> 1) * 64;

    float acc[4][8][4];
    #pragma unroll
    for (int i = 0; i < 4; i++)
        #pragma unroll
        for (int j = 0; j < 8; j++)
            #pragma unroll
            for (int k = 0; k < 4; k++) acc[i][j][k] = 0.0f;

    const int KT = K / BK;

    auto load_stage = [&](int it, int s) {
        const int kc = it * BK;
        const uint32_t st = sbase + s * STAGE_BYTES;
        const uint32_t sa = st + rA * ROWB + cA * 16;
        const size_t ga = (size_t)(m0 + rA) * K + kc + cA * 8;
        cp16(sa + AH_OFF,      Ah + ga);
        cp16(sa + AH_OFF + 16, Ah + ga + 8);
        const uint32_t sbb = st + BH_OFF + tid * ROWB;
        const size_t gb = (size_t)(n0 + tid) * K + kc;
        #pragma unroll
        for (int c = 0; c < 4; c++)
            cp16(sbb + c * 16, Bh + gb + c * 8);
    };

    load_stage(0, 0); CP_COMMIT();
    load_stage(1, 1); CP_COMMIT();

    for (int it = 0; it < KT; it++) {
        CP_WAIT1();
        __syncthreads();
        const int nx = it + 2;
        if (nx < KT) load_stage(nx, nx % 3);
        CP_COMMIT();

        const uint32_t st = sbase + (it % 3) * STAGE_BYTES;
        #pragma unroll
        for (int ks = 0; ks < 2; ks++) {
            const int kb  = (ks * 16 + (lane >> 4) * 8) * 2;
            const int kbB = (ks * 16 + ((lane >> 3) & 1) * 8) * 2;
            uint32_t a_h[4][4];
            #pragma unroll
            for (int mf = 0; mf < 4; mf++) {
                uint32_t ra = st + AH_OFF + (wm + mf * 16 + (lane & 15)) * ROWB + kb;
                ldsm4(a_h[mf], ra);
            }
            #pragma unroll
            for (int nf = 0; nf < 8; nf++) {
                uint32_t rb = st + BH_OFF + (wn + nf * 8 + (lane & 7)) * ROWB + kbB;
                uint32_t b_h[2];
                ldsm2(b_h, rb);
                #pragma unroll
                for (int mf = 0; mf < 4; mf++)
                    mma16816(acc[mf][nf], a_h[mf], b_h);
            }
        }
    }

    #pragma unroll
    for (int mf = 0; mf < 4; mf++) {
        const int m = m0 + wm + mf * 16 + (lane >> 2);
        #pragma unroll
        for (int nf = 0; nf < 8; nf++) {
            const int n = n0 + wn + nf * 8 + (lane & 3) * 2;
            float2 bv = *(const float2*)(bias + n);
            float* a = acc[mf][nf];
            float v0 = a[0] + bv.x, v1 = a[1] + bv.y;
            float v2 = a[2] + bv.x, v3 = a[3] + bv.y;
            if (EPI == 1) {
                float2 r0 = *(const float2*)(res + (size_t)m * N + n);
                float2 r1 = *(const float2*)(res + (size_t)(m + 8) * N + n);
                v0 += r0.x; v1 += r0.y; v2 += r1.x; v3 += r1.y;
            }
            if (EPI == 2) {
                v0 = gelu_exact(v0); v1 = gelu_exact(v1);
                v2 = gelu_exact(v2); v3 = gelu_exact(v3);
                *(uint32_t*)(Ch + (size_t)m * N + n)       = pack2h(v0, v1);
                *(uint32_t*)(Ch + (size_t)(m + 8) * N + n) = pack2h(v2, v3);
            } else if (EPI == 3) {
                uint32_t h0, l0, h1, l1;
                split2(v0, v1, h0, l0);
                split2(v2, v3, h1, l1);
                *(uint32_t*)(Ch + (size_t)m * N + n)       = h0;
                *(uint32_t*)(Cl + (size_t)m * N + n)       = l0;
                *(uint32_t*)(Ch + (size_t)(m + 8) * N + n) = h1;
                *(uint32_t*)(Cl + (size_t)(m + 8) * N + n) = l1;
            } else {
                *(float2*)(C + (size_t)m * N + n)       = make_float2(v0, v1);
                *(float2*)(C + (size_t)(m + 8) * N + n) = make_float2(v2, v3);
            }
        }
    }
}

// ----------------------------------------------------------------------------
// Tensor-core flash attention (fp16x2, unchanged numerics from R12).
// S = (Qh+Ql)*Kh ; softmax ; O += (Ph+Pl)*Vh.  Emits ctx hi only.
// ----------------------------------------------------------------------------
#define AROW 144
#define AQ_BYTES (64 * AROW)
#define AST (2 * AQ_BYTES)
#define ATT_SMEM (2 * AQ_BYTES + 2 * AST)  // 55296

__global__ __launch_bounds__(128) void attn_mma(
    const __half* __restrict__ qh, const __half* __restrict__ ql,
    __half* __restrict__ oh)
{
    extern __shared__ char smem[];
    const uint32_t sb = smem_to_u32(smem);
    const int tid  = threadIdx.x;
    const int w    = tid >> 5;
    const int lane = tid & 31;
    const int bh = blockIdx.y;
    const int b  = bh >> 4;
    const int h  = bh & 15;
    const int q0 = blockIdx.x * 64;

    const uint32_t QHs = sb;
    const uint32_t QLs = sb + AQ_BYTES;

    const int r  = tid >> 1;
    const int cb = (tid & 1) * 4;

    {
        const size_t g = (size_t)(b * SEQ + q0 + r) * D3 + h * HDIM + cb * 8;
        const uint32_t o = r * AROW + cb * 16;
        #pragma unroll
        for (int c = 0; c < 4; c++) {
            cp16(QHs + o + c * 16, qh + g + c * 8);
            cp16(QLs + o + c * 16, ql + g + c * 8);
        }
    }
    auto load_kv = [&](int kt, int s) {
        const uint32_t st = sb + 2 * AQ_BYTES + s * AST;
        const size_t gk = (size_t)(b * SEQ + kt * 64 + r) * D3 + DMODEL + h * HDIM + cb * 8;
        const size_t gv = gk + DMODEL;
        const uint32_t o = r * AROW + cb * 16;
        #pragma unroll
        for (int c = 0; c < 4; c++) {
            cp16(st + o + c * 16,            qh + gk + c * 8);
            cp16(st + AQ_BYTES + o + c * 16, qh + gv + c * 8);
        }
    };
    load_kv(0, 0); CP_COMMIT();
    load_kv(1, 1); CP_COMMIT();

    uint32_t qfh[4][4], qfl[4][4];
    float O[8][4];
    #pragma unroll
    for (int i = 0; i < 8; i++)
        #pragma unroll
        for (int j = 0; j < 4; j++) O[i][j] = 0.0f;
    float m0 = -1e30f, m1 = -1e30f, l0 = 0.0f, l1 = 0.0f;

    for (int kt = 0; kt < SEQ / 64; kt++) {
        CP_WAIT1();
        __syncthreads();
        if (kt == 0) {
            #pragma unroll
            for (int kf = 0; kf < 4; kf++) {
                uint32_t qa = QHs + (w * 16 + (lane & 15)) * AROW + kf * 32 + (lane >> 4) * 16;
                ldsm4(qfh[kf], qa);
                ldsm4(qfl[kf], qa + AQ_BYTES);
            }
        }
        const uint32_t st = sb + 2 * AQ_BYTES + (kt & 1) * AST;

        float s[8][4];
        #pragma unroll
        for (int i = 0; i < 8; i++)
            #pragma unroll
            for (int j = 0; j < 4; j++) s[i][j] = 0.0f;
        #pragma unroll
        for (int kf = 0; kf < 4; kf++) {
            #pragma unroll
            for (int nf = 0; nf < 8; nf++) {
                uint32_t ka = st + (nf * 8 + (lane & 7)) * AROW + kf * 32 + ((lane >> 3) & 1) * 16;
                uint32_t b_h[2];
                ldsm2(b_h, ka);
                mma16816(s[nf], qfh[kf], b_h);
                mma16816(s[nf], qfl[kf], b_h);
            }
        }

        float mx0 = -1e30f, mx1 = -1e30f;
        #pragma unroll
        for (int nf = 0; nf < 8; nf++) {
            s[nf][0] *= 0.125f; s[nf][1] *= 0.125f;
            s[nf][2] *= 0.125f; s[nf][3] *= 0.125f;
            mx0 = fmaxf(mx0, fmaxf(s[nf][0], s[nf][1]));
            mx1 = fmaxf(mx1, fmaxf(s[nf][2], s[nf][3]));
        }
        mx0 = fmaxf(mx0, __shfl_xor_sync(0xffffffffu, mx0, 1));
        mx0 = fmaxf(mx0, __shfl_xor_sync(0xffffffffu, mx0, 2));
        mx1 = fmaxf(mx1, __shfl_xor_sync(0xffffffffu, mx1, 1));
        mx1 = fmaxf(mx1, __shfl_xor_sync(0xffffffffu, mx1, 2));
        float mn0 = fmaxf(m0, mx0), mn1 = fmaxf(m1, mx1);
        float cr0 = __expf(m0 - mn0), cr1 = __expf(m1 - mn1);
        float sm0 = 0.0f, sm1 = 0.0f;
        #pragma unroll
        for (int nf = 0; nf < 8; nf++) {
            s[nf][0] = __expf(s[nf][0] - mn0); sm0 += s[nf][0];
            s[nf][1] = __expf(s[nf][1] - mn0); sm0 += s[nf][1];
            s[nf][2] = __expf(s[nf][2] - mn1); sm1 += s[nf][2];
            s[nf][3] = __expf(s[nf][3] - mn1); sm1 += s[nf][3];
        }
        sm0 += __shfl_xor_sync(0xffffffffu, sm0, 1);
        sm0 += __shfl_xor_sync(0xffffffffu, sm0, 2);
        sm1 += __shfl_xor_sync(0xffffffffu, sm1, 1);
        sm1 += __shfl_xor_sync(0xffffffffu, sm1, 2);
        l0 = l0 * cr0 + sm0; m0 = mn0;
        l1 = l1 * cr1 + sm1; m1 = mn1;
        #pragma unroll
        for (int nf = 0; nf < 8; nf++) {
            O[nf][0] *= cr0; O[nf][1] *= cr0;
            O[nf][2] *= cr1; O[nf][3] *= cr1;
        }

        #pragma unroll
        for (int kf = 0; kf < 4; kf++) {
            uint32_t pa[4], pl[4];
            split2(s[2*kf][0],   s[2*kf][1],   pa[0], pl[0]);
            split2(s[2*kf][2],   s[2*kf][3],   pa[1], pl[1]);
            split2(s[2*kf+1][0], s[2*kf+1][1], pa[2], pl[2]);
            split2(s[2*kf+1][2], s[2*kf+1][3], pa[3], pl[3]);
            #pragma unroll
            for (int nf = 0; nf < 8; nf++) {
                uint32_t va = st + AQ_BYTES + (kf * 16 + (lane & 15)) * AROW + nf * 16;
                uint32_t b_h[2];
                ldsm2t(b_h, va);
                mma16816(O[nf], pa, b_h);
                mma16816(O[nf], pl, b_h);
            }
        }

        __syncthreads();
        if (kt + 2 < SEQ / 64) load_kv(kt + 2, kt & 1);
        CP_COMMIT();
    }

    // ---- write ctx hi only ----
    {
        float i0 = 1.0f / l0, i1 = 1.0f / l1;
        const int mr = q0 + w * 16 + (lane >> 2);
        const size_t row0 = (size_t)(b * SEQ + mr) * DMODEL;
        const size_t row1 = row0 + 8 * DMODEL;
        #pragma unroll
        for (int nf = 0; nf < 8; nf++) {
            const int n = h * HDIM + nf * 8 + (lane & 3) * 2;
            *(uint32_t*)(oh + row0 + n) = pack2h(O[nf][0] * i0, O[nf][1] * i0);
            *(uint32_t*)(oh + row1 + n) = pack2h(O[nf][2] * i1, O[nf][3] * i1);
        }
    }
}

// ----------------------------------------------------------------------------
// LayerNorm; SPLIT=1 additionally emits fp16 hi of the output
// ----------------------------------------------------------------------------
template <int SPLIT>
__global__ __launch_bounds__(256) void ln_kernel(
    const float* __restrict__ x, const float* __restrict__ g,
    const float* __restrict__ beta, float* __restrict__ y,
    __half* __restrict__ yh)
{
    const int row = blockIdx.x;
    const int tid = threadIdx.x;
    const float* xr = x + (size_t)row * DMODEL;

    float4 v = *(const float4*)(xr + tid * 4);
    float s  = v.x + v.y + v.z + v.w;
    float sq = v.x*v.x + v.y*v.y + v.z*v.z + v.w*v.w;

    #pragma unroll
    for (int off = 16; off > 0; off >>= 1) {
        s  += __shfl_xor_sync(0xffffffffu, s,  off);
        sq += __shfl_xor_sync(0xffffffffu, sq, off);
    }
    __shared__ float ss[8], ssq[8];
    if ((tid & 31) == 0) { ss[tid >> 5] = s; ssq[tid >> 5] = sq; }
    __syncthreads();
    float tot = 0.0f, totq = 0.0f;
    #pragma unroll
    for (int i = 0; i < 8; i++) { tot += ss[i]; totq += ssq[i]; }

    const float mu   = tot * (1.0f / DMODEL);
    const float var  = totq * (1.0f / DMODEL) - mu * mu;
    const float rstd = rsqrtf(var + 1e-5f);

    float4 gg = *(const float4*)(g + tid * 4);
    float4 bb = *(const float4*)(beta + tid * 4);
    float4 o;
    o.x = (v.x - mu) * rstd * gg.x + bb.x;
    o.y = (v.y - mu) * rstd * gg.y + bb.y;
    o.z = (v.z - mu) * rstd * gg.z + bb.z;
    o.w = (v.w - mu) * rstd * gg.w + bb.w;
    *(float4*)(y + (size_t)row * DMODEL + tid * 4) = o;

    if (SPLIT) {
        ((uint2*)(yh + (size_t)row * DMODEL))[tid] =
            make_uint2(pack2h(o.x, o.y), pack2h(o.z, o.w));
    }
}

// ----------------------------------------------------------------------------
// kernel_launch
// Inputs: 0 X, 1 W_qkv, 2 b_qkv, 3 W_out, 4 b_out, 5 ln1_g, 6 ln1_b,
//         7 ln2_g, 8 ln2_b, 9 W_ff1, 10 b_ff1, 11 W_ff2, 12 b_ff2
// ----------------------------------------------------------------------------
extern "C" void kernel_launch(void* const* d_in, const int* in_sizes, int n_in,
                              void* d_out, int out_size)
{
    const float* X      = (const float*)d_in[0];
    const float* W_qkv  = (const float*)d_in[1];
    const float* b_qkv  = (const float*)d_in[2];
    const float* W_out  = (const float*)d_in[3];
    const float* b_out  = (const float*)d_in[4];
    const float* ln1_g  = (const float*)d_in[5];
    const float* ln1_b  = (const float*)d_in[6];
    const float* ln2_g  = (const float*)d_in[7];
    const float* ln2_b  = (const float*)d_in[8];
    const float* W_ff1  = (const float*)d_in[9];
    const float* b_ff1  = (const float*)d_in[10];
    const float* W_ff2  = (const float*)d_in[11];
    const float* b_ff2  = (const float*)d_in[12];
    float* out = (float*)d_out;

    float *tmp, *x1;
    __half *qkh, *qkl, *ah, *fh;
    __half *wqh, *woh, *w1h, *w2h;
    cudaGetSymbolAddress((void**)&qkh, g_qkv_h);
    cudaGetSymbolAddress((void**)&qkl, g_qkv_l);
    cudaGetSymbolAddress((void**)&tmp, g_tmp);
    cudaGetSymbolAddress((void**)&x1,  g_x1);
    cudaGetSymbolAddress((void**)&ah,  g_act_h);
    cudaGetSymbolAddress((void**)&fh,  g_ffh_h);
    cudaGetSymbolAddress((void**)&wqh, g_wqkv_h);
    cudaGetSymbolAddress((void**)&woh, g_wout_h);
    cudaGetSymbolAddress((void**)&w1h, g_wff1_h);
    cudaGetSymbolAddress((void**)&w2h, g_wff2_h);

    cudaFuncSetAttribute(gemm_mma<0>, cudaFuncAttributeMaxDynamicSharedMemorySize, GEMM_SMEM);
    cudaFuncSetAttribute(gemm_mma<1>, cudaFuncAttributeMaxDynamicSharedMemorySize, GEMM_SMEM);
    cudaFuncSetAttribute(gemm_mma<2>, cudaFuncAttributeMaxDynamicSharedMemorySize, GEMM_SMEM);
    cudaFuncSetAttribute(gemm_mma<3>, cudaFuncAttributeMaxDynamicSharedMemorySize, GEMM_SMEM);
    cudaFuncSetAttribute(attn_mma, cudaFuncAttributeMaxDynamicSharedMemorySize, ATT_SMEM);

    dim3 tb(32, 8);
    // 0) transpose weights -> [N,K] fp16
    transpose_h_kernel<<<dim3(D3   / 32, DMODEL / 32), tb>>>(W_qkv, wqh, DMODEL, D3);
    transpose_h_kernel<<<dim3(DMODEL / 32, DMODEL / 32), tb>>>(W_out, woh, DMODEL, DMODEL);
    transpose_h_kernel<<<dim3(DFF  / 32, DMODEL / 32), tb>>>(W_ff1, w1h, DMODEL, DFF);
    transpose_h_kernel<<<dim3(DMODEL / 32, DFF / 32), tb>>>(W_ff2, w2h, DFF, DMODEL);

    // 1) convert X -> fp16; QKV projection -> hi + lo (lo feeds attention Q)
    convert_h_kernel<<<(M_ROWS * DMODEL / 4) / 256, 256>>>(X, ah, M_ROWS * DMODEL / 4);
    gemm_mma<3><<<dim3(D3 / BN, M_ROWS / BM), 256, GEMM_SMEM>>>(
        ah, wqh, b_qkv, nullptr, nullptr, qkh, qkl, D3, DMODEL);

    // 2) tensor-core attention -> ctx hi (reuses act buffer)
    attn_mma<<<dim3(SEQ / 64, 8 * NHEAD), 128, ATT_SMEM>>>(qkh, qkl, ah);

    // 3) out-proj + residual(X) -> tmp fp32
    gemm_mma<1><<<dim3(DMODEL / BN, M_ROWS / BM), 256, GEMM_SMEM>>>(
        ah, woh, b_out, X, tmp, nullptr, nullptr, DMODEL, DMODEL);

    // 4) LN1 -> x1 fp32 + fp16 hi
    ln_kernel<1><<<M_ROWS, 256>>>(tmp, ln1_g, ln1_b, x1, ah);

    // 5) FF1 + GELU -> fp16 hi
    gemm_mma<2><<<dim3(DFF / BN, M_ROWS / BM), 256, GEMM_SMEM>>>(
        ah, w1h, b_ff1, nullptr, nullptr, fh, nullptr, DFF, DMODEL);

    // 6) FF2 + residual(x1) -> tmp fp32
    gemm_mma<1><<<dim3(DMODEL / BN, M_ROWS / BM), 256, GEMM_SMEM>>>(
        fh, w2h, b_ff2, x1, tmp, nullptr, nullptr, DMODEL, DFF);

    // 7) LN2 -> out
    ln_kernel<0><<<M_ROWS, 256>>>(tmp, ln2_g, ln2_b, out, nullptr);
}

// round 14
// speedup vs baseline: 2.0842x; 1.0386x over previous
#include <cuda_runtime.h>
#include <cuda_fp16.h>
#include <math.h>
#include <stdint.h>

// ----------------------------------------------------------------------------
// Problem constants: B=8, T=1024, D=1024, H=16, HD=64.  M = B*T = 8192.
// ----------------------------------------------------------------------------
#define M_ROWS 8192
#define DMODEL 1024
#define D3     3072
#define DFF    4096
#define NHEAD  16
#define HDIM   64
#define SEQ    1024

// ----------------------------------------------------------------------------
// Scratch (device globals -- no cudaMalloc allowed)
// Pure-fp16 tensor path everywhere; fp32 only for pre-LN accumulation.
// ----------------------------------------------------------------------------
__device__ __half g_qkv_h[M_ROWS * D3];       // QKV fp16
__device__ float g_tmp[M_ROWS * DMODEL];      // fp32 pre-LN buffers
__device__ float g_x1 [M_ROWS * DMODEL];
__device__ __half g_act_h[M_ROWS * DMODEL];   // activation fp16 (X / ctx / x1)
__device__ __half g_ffh_h[M_ROWS * DFF];      // FF1 out fp16
// weights, transposed to [N,K], fp16
__device__ __half g_wqkv_h[DMODEL * D3];
__device__ __half g_wout_h[DMODEL * DMODEL];
__device__ __half g_wff1_h[DMODEL * DFF];
__device__ __half g_wff2_h[DFF * DMODEL];

// ----------------------------------------------------------------------------
// PTX helpers (compute_103-baseline legal: cp.async / ldmatrix / mma.sync)
// ----------------------------------------------------------------------------
__device__ __forceinline__ uint32_t smem_to_u32(const void* smem_ptr) {
    uint32_t addr;
    asm("{ .reg .u64 tmp; cvta.to.shared.u64 tmp, %1; cvt.u32.u64 %0, tmp; }"
        : "=r"(addr) : "l"(smem_ptr));
    return addr;
}

__device__ __forceinline__ void cp16(uint32_t smem_addr, const void* gptr) {
    asm volatile("cp.async.cg.shared.global [%0], [%1], 16;"
                 :: "r"(smem_addr), "l"(gptr));
}
#define CP_COMMIT() asm volatile("cp.async.commit_group;" ::: "memory")
#define CP_WAIT1()  asm volatile("cp.async.wait_group 1;" ::: "memory")

__device__ __forceinline__ void ldsm4(uint32_t* d, uint32_t addr) {
    asm volatile("ldmatrix.sync.aligned.m8n8.x4.shared.b16 {%0,%1,%2,%3}, [%4];"
        : "=r"(d[0]), "=r"(d[1]), "=r"(d[2]), "=r"(d[3]) : "r"(addr));
}
__device__ __forceinline__ void ldsm2(uint32_t* d, uint32_t addr) {
    asm volatile("ldmatrix.sync.aligned.m8n8.x2.shared.b16 {%0,%1}, [%2];"
        : "=r"(d[0]), "=r"(d[1]) : "r"(addr));
}
__device__ __forceinline__ void ldsm2t(uint32_t* d, uint32_t addr) {
    asm volatile("ldmatrix.sync.aligned.m8n8.x2.trans.shared.b16 {%0,%1}, [%2];"
        : "=r"(d[0]), "=r"(d[1]) : "r"(addr));
}

__device__ __forceinline__ void mma16816(float* c, const uint32_t* a, const uint32_t* b) {
    asm volatile("mma.sync.aligned.m16n8k16.row.col.f32.f16.f16.f32 "
        "{%0,%1,%2,%3}, {%4,%5,%6,%7}, {%8,%9}, {%0,%1,%2,%3};"
        : "+f"(c[0]), "+f"(c[1]), "+f"(c[2]), "+f"(c[3])
        : "r"(a[0]), "r"(a[1]), "r"(a[2]), "r"(a[3]), "r"(b[0]), "r"(b[1]));
}

__device__ __forceinline__ uint32_t pack2h(float a, float b) {
    __half2 hp(__float2half(a), __float2half(b));
    return *(uint32_t*)&hp;
}

__global__ __launch_bounds__(256) void convert_h_kernel(
    const float* __restrict__ x, __half* __restrict__ h, int n4)
{
    int i = blockIdx.x * 256 + threadIdx.x;
    if (i >= n4) return;
    float4 v = ((const float4*)x)[i];
    ((uint2*)h)[i] = make_uint2(pack2h(v.x, v.y), pack2h(v.z, v.w));
}

// W [K,N] fp32 row-major -> Wt [N,K] fp16 (32x32 tiles)
__global__ __launch_bounds__(256) void transpose_h_kernel(
    const float* __restrict__ W, __half* __restrict__ h, int K, int N)
{
    __shared__ float t[32][33];
    const int tx = threadIdx.x;
    const int ty = threadIdx.y;
    const int k0 = blockIdx.y * 32;
    const int n0 = blockIdx.x * 32;
    #pragma unroll
    for (int r = 0; r < 4; r++)
        t[ty * 4 + r][tx] = W[(size_t)(k0 + ty * 4 + r) * N + n0 + tx];
    __syncthreads();
    #pragma unroll
    for (int r = 0; r < 4; r++) {
        int n = n0 + ty * 4 + r;
        h[(size_t)n * K + k0 + tx] = __float2half(t[tx][ty * 4 + r]);
    }
}

// ----------------------------------------------------------------------------
// Pure-fp16 mma.sync GEMM:  C[M,N] = A[M,K] @ Bt[N,K]^T + bias (+ epilogue)
// Tile 128x256, BK=64, 256 threads (8 warps, 2x4 grid, each 64x64),
// 3-stage cp.async.  ROWB=144 (64 halves + 16B pad) -> conflict-free ldsm.
// EPI: 1 = bias + residual -> fp32;  2 = bias + exact GELU -> fp16;
//      3 = bias -> fp16
// ----------------------------------------------------------------------------
#define BM 128
#define BN 256
#define BK 64
#define ROWB 144
#define AH_OFF 0
#define BH_OFF 18432
#define STAGE_BYTES 55296
#define GEMM_SMEM (3 * STAGE_BYTES)   // 165888

__device__ __forceinline__ float gelu_exact(float x) {
    return 0.5f * x * (1.0f + erff(x * 0.70710678118654752440f));
}

template <int EPI>
__global__ __launch_bounds__(256) void gemm_mma(
    const __half* __restrict__ Ah, const __half* __restrict__ Bh,
    const float* __restrict__ bias, const float* __restrict__ res,
    float* __restrict__ C, __half* __restrict__ Ch, int N, int K)
{
    extern __shared__ char smem[];
    const uint32_t sbase = smem_to_u32(smem);
    const int tid  = threadIdx.x;
    const int wid  = tid >> 5;
    const int lane = tid & 31;
    const int m0 = blockIdx.y * BM;
    const int n0 = blockIdx.x * BN;

    // A loader: 2 threads/row, 4 chunks each; B loader: 1 thread/row, 8 chunks
    const int rA = tid >> 1;
    const int cA = (tid & 1) * 4;

    // warp tile 64x64
    const int wm = (wid & 1) * 64;
    const int wn = (wid >> 1) * 64;

    float acc[4][8][4];
    #pragma unroll
    for (int i = 0; i < 4; i++)
        #pragma unroll
        for (int j = 0; j < 8; j++)
            #pragma unroll
            for (int k = 0; k < 4; k++) acc[i][j][k] = 0.0f;

    const int KT = K / BK;

    auto load_stage = [&](int it, int s) {
        const int kc = it * BK;
        const uint32_t st = sbase + s * STAGE_BYTES;
        const uint32_t sa = st + AH_OFF + rA * ROWB + cA * 16;
        const size_t ga = (size_t)(m0 + rA) * K + kc + cA * 8;
        #pragma unroll
        for (int c = 0; c < 4; c++)
            cp16(sa + c * 16, Ah + ga + c * 8);
        const uint32_t sbb = st + BH_OFF + tid * ROWB;
        const size_t gb = (size_t)(n0 + tid) * K + kc;
        #pragma unroll
        for (int c = 0; c < 8; c++)
            cp16(sbb + c * 16, Bh + gb + c * 8);
    };

    load_stage(0, 0); CP_COMMIT();
    load_stage(1, 1); CP_COMMIT();

    for (int it = 0; it < KT; it++) {
        CP_WAIT1();
        __syncthreads();
        const int nx = it + 2;
        if (nx < KT) load_stage(nx, nx % 3);
        CP_COMMIT();

        const uint32_t st = sbase + (it % 3) * STAGE_BYTES;
        #pragma unroll
        for (int ks = 0; ks < 4; ks++) {
            const int kb  = (ks * 16 + (lane >> 4) * 8) * 2;
            const int kbB = (ks * 16 + ((lane >> 3) & 1) * 8) * 2;
            uint32_t a_h[4][4];
            #pragma unroll
            for (int mf = 0; mf < 4; mf++) {
                uint32_t ra = st + AH_OFF + (wm + mf * 16 + (lane & 15)) * ROWB + kb;
                ldsm4(a_h[mf], ra);
            }
            #pragma unroll
            for (int nf = 0; nf < 8; nf++) {
                uint32_t rb = st + BH_OFF + (wn + nf * 8 + (lane & 7)) * ROWB + kbB;
                uint32_t b_h[2];
                ldsm2(b_h, rb);
                #pragma unroll
                for (int mf = 0; mf < 4; mf++)
                    mma16816(acc[mf][nf], a_h[mf], b_h);
            }
        }
    }

    #pragma unroll
    for (int mf = 0; mf < 4; mf++) {
        const int m = m0 + wm + mf * 16 + (lane >> 2);
        #pragma unroll
        for (int nf = 0; nf < 8; nf++) {
            const int n = n0 + wn + nf * 8 + (lane & 3) * 2;
            float2 bv = *(const float2*)(bias + n);
            float* a = acc[mf][nf];
            float v0 = a[0] + bv.x, v1 = a[1] + bv.y;
            float v2 = a[2] + bv.x, v3 = a[3] + bv.y;
            if (EPI == 1) {
                float2 r0 = *(const float2*)(res + (size_t)m * N + n);
                float2 r1 = *(const float2*)(res + (size_t)(m + 8) * N + n);
                v0 += r0.x; v1 += r0.y; v2 += r1.x; v3 += r1.y;
            }
            if (EPI == 2) {
                v0 = gelu_exact(v0); v1 = gelu_exact(v1);
                v2 = gelu_exact(v2); v3 = gelu_exact(v3);
            }
            if (EPI >= 2) {
                *(uint32_t*)(Ch + (size_t)m * N + n)       = pack2h(v0, v1);
                *(uint32_t*)(Ch + (size_t)(m + 8) * N + n) = pack2h(v2, v3);
            } else {
                *(float2*)(C + (size_t)m * N + n)       = make_float2(v0, v1);
                *(float2*)(C + (size_t)(m + 8) * N + n) = make_float2(v2, v3);
            }
        }
    }
}

// ----------------------------------------------------------------------------
// Tensor-core flash attention (pure fp16 operands, fp32 accum/softmax).
// CTA: 64 q rows x one (b,h); 4 warps x 16 q rows; K tiles of 64 keys.
// S = Q*K^T (1 MMA); softmax in mma layout; O += P*V (1 MMA, ldmatrix.trans).
// ----------------------------------------------------------------------------
#define AROW 144
#define AQ_BYTES (64 * AROW)           // 9216
#define AST (2 * AQ_BYTES)             // Kh,Vh = 18432
#define ATT_SMEM (AQ_BYTES + 2 * AST)  // 46080

__global__ __launch_bounds__(128) void attn_mma(
    const __half* __restrict__ qkv, __half* __restrict__ oh)
{
    extern __shared__ char smem[];
    const uint32_t sb = smem_to_u32(smem);
    const int tid  = threadIdx.x;
    const int w    = tid >> 5;
    const int lane = tid & 31;
    const int bh = blockIdx.y;
    const int b  = bh >> 4;
    const int h  = bh & 15;
    const int q0 = blockIdx.x * 64;

    const uint32_t QHs = sb;
    const int r  = tid >> 1;
    const int cb = (tid & 1) * 4;

    {
        const size_t g = (size_t)(b * SEQ + q0 + r) * D3 + h * HDIM + cb * 8;
        const uint32_t o = r * AROW + cb * 16;
        #pragma unroll
        for (int c = 0; c < 4; c++)
            cp16(QHs + o + c * 16, qkv + g + c * 8);
    }
    auto load_kv = [&](int kt, int s) {
        const uint32_t st = sb + AQ_BYTES + s * AST;
        const size_t gk = (size_t)(b * SEQ + kt * 64 + r) * D3 + DMODEL + h * HDIM + cb * 8;
        const size_t gv = gk + DMODEL;
        const uint32_t o = r * AROW + cb * 16;
        #pragma unroll
        for (int c = 0; c < 4; c++) {
            cp16(st + o + c * 16,            qkv + gk + c * 8);
            cp16(st + AQ_BYTES + o + c * 16, qkv + gv + c * 8);
        }
    };
    load_kv(0, 0); CP_COMMIT();
    load_kv(1, 1); CP_COMMIT();

    uint32_t qfh[4][4];
    float O[8][4];
    #pragma unroll
    for (int i = 0; i < 8; i++)
        #pragma unroll
        for (int j = 0; j < 4; j++) O[i][j] = 0.0f;
    float m0 = -1e30f, m1 = -1e30f, l0 = 0.0f, l1 = 0.0f;

    for (int kt = 0; kt < SEQ / 64; kt++) {
        CP_WAIT1();
        __syncthreads();
        if (kt == 0) {
            #pragma unroll
            for (int kf = 0; kf < 4; kf++) {
                uint32_t qa = QHs + (w * 16 + (lane & 15)) * AROW + kf * 32 + (lane >> 4) * 16;
                ldsm4(qfh[kf], qa);
            }
        }
        const uint32_t st = sb + AQ_BYTES + (kt & 1) * AST;

        // ---- S = Q K^T ----
        float s[8][4];
        #pragma unroll
        for (int i = 0; i < 8; i++)
            #pragma unroll
            for (int j = 0; j < 4; j++) s[i][j] = 0.0f;
        #pragma unroll
        for (int kf = 0; kf < 4; kf++) {
            #pragma unroll
            for (int nf = 0; nf < 8; nf++) {
                uint32_t ka = st + (nf * 8 + (lane & 7)) * AROW + kf * 32 + ((lane >> 3) & 1) * 16;
                uint32_t b_h[2];
                ldsm2(b_h, ka);
                mma16816(s[nf], qfh[kf], b_h);
            }
        }

        // ---- online softmax in mma layout ----
        float mx0 = -1e30f, mx1 = -1e30f;
        #pragma unroll
        for (int nf = 0; nf < 8; nf++) {
            s[nf][0] *= 0.125f; s[nf][1] *= 0.125f;
            s[nf][2] *= 0.125f; s[nf][3] *= 0.125f;
            mx0 = fmaxf(mx0, fmaxf(s[nf][0], s[nf][1]));
            mx1 = fmaxf(mx1, fmaxf(s[nf][2], s[nf][3]));
        }
        mx0 = fmaxf(mx0, __shfl_xor_sync(0xffffffffu, mx0, 1));
        mx0 = fmaxf(mx0, __shfl_xor_sync(0xffffffffu, mx0, 2));
        mx1 = fmaxf(mx1, __shfl_xor_sync(0xffffffffu, mx1, 1));
        mx1 = fmaxf(mx1, __shfl_xor_sync(0xffffffffu, mx1, 2));
        float mn0 = fmaxf(m0, mx0), mn1 = fmaxf(m1, mx1);
        float cr0 = __expf(m0 - mn0), cr1 = __expf(m1 - mn1);
        float sm0 = 0.0f, sm1 = 0.0f;
        #pragma unroll
        for (int nf = 0; nf < 8; nf++) {
            s[nf][0] = __expf(s[nf][0] - mn0); sm0 += s[nf][0];
            s[nf][1] = __expf(s[nf][1] - mn0); sm0 += s[nf][1];
            s[nf][2] = __expf(s[nf][2] - mn1); sm1 += s[nf][2];
            s[nf][3] = __expf(s[nf][3] - mn1); sm1 += s[nf][3];
        }
        sm0 += __shfl_xor_sync(0xffffffffu, sm0, 1);
        sm0 += __shfl_xor_sync(0xffffffffu, sm0, 2);
        sm1 += __shfl_xor_sync(0xffffffffu, sm1, 1);
        sm1 += __shfl_xor_sync(0xffffffffu, sm1, 2);
        l0 = l0 * cr0 + sm0; m0 = mn0;
        l1 = l1 * cr1 + sm1; m1 = mn1;
        #pragma unroll
        for (int nf = 0; nf < 8; nf++) {
            O[nf][0] *= cr0; O[nf][1] *= cr0;
            O[nf][2] *= cr1; O[nf][3] *= cr1;
        }

        // ---- O += P V ----
        #pragma unroll
        for (int kf = 0; kf < 4; kf++) {
            uint32_t pa[4];
            pa[0] = pack2h(s[2*kf][0],   s[2*kf][1]);
            pa[1] = pack2h(s[2*kf][2],   s[2*kf][3]);
            pa[2] = pack2h(s[2*kf+1][0], s[2*kf+1][1]);
            pa[3] = pack2h(s[2*kf+1][2], s[2*kf+1][3]);
            #pragma unroll
            for (int nf = 0; nf < 8; nf++) {
                uint32_t va = st + AQ_BYTES + (kf * 16 + (lane & 15)) * AROW + nf * 16;
                uint32_t b_h[2];
                ldsm2t(b_h, va);
                mma16816(O[nf], pa, b_h);
            }
        }

        __syncthreads();
        if (kt + 2 < SEQ / 64) load_kv(kt + 2, kt & 1);
        CP_COMMIT();
    }

    // ---- write ctx fp16 ----
    {
        float i0 = 1.0f / l0, i1 = 1.0f / l1;
        const int mr = q0 + w * 16 + (lane >> 2);
        const size_t row0 = (size_t)(b * SEQ + mr) * DMODEL;
        const size_t row1 = row0 + 8 * DMODEL;
        #pragma unroll
        for (int nf = 0; nf < 8; nf++) {
            const int n = h * HDIM + nf * 8 + (lane & 3) * 2;
            *(uint32_t*)(oh + row0 + n) = pack2h(O[nf][0] * i0, O[nf][1] * i0);
            *(uint32_t*)(oh + row1 + n) = pack2h(O[nf][2] * i1, O[nf][3] * i1);
        }
    }
}

// ----------------------------------------------------------------------------
// LayerNorm; SPLIT=1 additionally emits fp16 of the output
// ----------------------------------------------------------------------------
template <int SPLIT>
__global__ __launch_bounds__(256) void ln_kernel(
    const float* __restrict__ x, const float* __restrict__ g,
    const float* __restrict__ beta, float* __restrict__ y,
    __half* __restrict__ yh)
{
    const int row = blockIdx.x;
    const int tid = threadIdx.x;
    const float* xr = x + (size_t)row * DMODEL;

    float4 v = *(const float4*)(xr + tid * 4);
    float s  = v.x + v.y + v.z + v.w;
    float sq = v.x*v.x + v.y*v.y + v.z*v.z + v.w*v.w;

    #pragma unroll
    for (int off = 16; off > 0; off >>= 1) {
        s  += __shfl_xor_sync(0xffffffffu, s,  off);
        sq += __shfl_xor_sync(0xffffffffu, sq, off);
    }
    __shared__ float ss[8], ssq[8];
    if ((tid & 31) == 0) { ss[tid >> 5] = s; ssq[tid >> 5] = sq; }
    __syncthreads();
    float tot = 0.0f, totq = 0.0f;
    #pragma unroll
    for (int i = 0; i < 8; i++) { tot += ss[i]; totq += ssq[i]; }

    const float mu   = tot * (1.0f / DMODEL);
    const float var  = totq * (1.0f / DMODEL) - mu * mu;
    const float rstd = rsqrtf(var + 1e-5f);

    float4 gg = *(const float4*)(g + tid * 4);
    float4 bb = *(const float4*)(beta + tid * 4);
    float4 o;
    o.x = (v.x - mu) * rstd * gg.x + bb.x;
    o.y = (v.y - mu) * rstd * gg.y + bb.y;
    o.z = (v.z - mu) * rstd * gg.z + bb.z;
    o.w = (v.w - mu) * rstd * gg.w + bb.w;
    *(float4*)(y + (size_t)row * DMODEL + tid * 4) = o;

    if (SPLIT) {
        ((uint2*)(yh + (size_t)row * DMODEL))[tid] =
            make_uint2(pack2h(o.x, o.y), pack2h(o.z, o.w));
    }
}

// ----------------------------------------------------------------------------
// kernel_launch
// Inputs: 0 X, 1 W_qkv, 2 b_qkv, 3 W_out, 4 b_out, 5 ln1_g, 6 ln1_b,
//         7 ln2_g, 8 ln2_b, 9 W_ff1, 10 b_ff1, 11 W_ff2, 12 b_ff2
// ----------------------------------------------------------------------------
extern "C" void kernel_launch(void* const* d_in, const int* in_sizes, int n_in,
                              void* d_out, int out_size)
{
    const float* X      = (const float*)d_in[0];
    const float* W_qkv  = (const float*)d_in[1];
    const float* b_qkv  = (const float*)d_in[2];
    const float* W_out  = (const float*)d_in[3];
    const float* b_out  = (const float*)d_in[4];
    const float* ln1_g  = (const float*)d_in[5];
    const float* ln1_b  = (const float*)d_in[6];
    const float* ln2_g  = (const float*)d_in[7];
    const float* ln2_b  = (const float*)d_in[8];
    const float* W_ff1  = (const float*)d_in[9];
    const float* b_ff1  = (const float*)d_in[10];
    const float* W_ff2  = (const float*)d_in[11];
    const float* b_ff2  = (const float*)d_in[12];
    float* out = (float*)d_out;

    float *tmp, *x1;
    __half *qkh, *ah, *fh;
    __half *wqh, *woh, *w1h, *w2h;
    cudaGetSymbolAddress((void**)&qkh, g_qkv_h);
    cudaGetSymbolAddress((void**)&tmp, g_tmp);
    cudaGetSymbolAddress((void**)&x1,  g_x1);
    cudaGetSymbolAddress((void**)&ah,  g_act_h);
    cudaGetSymbolAddress((void**)&fh,  g_ffh_h);
    cudaGetSymbolAddress((void**)&wqh, g_wqkv_h);
    cudaGetSymbolAddress((void**)&woh, g_wout_h);
    cudaGetSymbolAddress((void**)&w1h, g_wff1_h);
    cudaGetSymbolAddress((void**)&w2h, g_wff2_h);

    cudaFuncSetAttribute(gemm_mma<1>, cudaFuncAttributeMaxDynamicSharedMemorySize, GEMM_SMEM);
    cudaFuncSetAttribute(gemm_mma<2>, cudaFuncAttributeMaxDynamicSharedMemorySize, GEMM_SMEM);
    cudaFuncSetAttribute(gemm_mma<3>, cudaFuncAttributeMaxDynamicSharedMemorySize, GEMM_SMEM);
    cudaFuncSetAttribute(attn_mma, cudaFuncAttributeMaxDynamicSharedMemorySize, ATT_SMEM);

    dim3 tb(32, 8);
    // 0) transpose weights -> [N,K] fp16
    transpose_h_kernel<<<dim3(D3   / 32, DMODEL / 32), tb>>>(W_qkv, wqh, DMODEL, D3);
    transpose_h_kernel<<<dim3(DMODEL / 32, DMODEL / 32), tb>>>(W_out, woh, DMODEL, DMODEL);
    transpose_h_kernel<<<dim3(DFF  / 32, DMODEL / 32), tb>>>(W_ff1, w1h, DMODEL, DFF);
    transpose_h_kernel<<<dim3(DMODEL / 32, DFF / 32), tb>>>(W_ff2, w2h, DFF, DMODEL);

    // 1) convert X -> fp16; QKV projection -> fp16
    convert_h_kernel<<<(M_ROWS * DMODEL / 4) / 256, 256>>>(X, ah, M_ROWS * DMODEL / 4);
    gemm_mma<3><<<dim3(D3 / BN, M_ROWS / BM), 256, GEMM_SMEM>>>(
        ah, wqh, b_qkv, nullptr, nullptr, qkh, D3, DMODEL);

    // 2) tensor-core attention -> ctx fp16 (reuses act buffer)
    attn_mma<<<dim3(SEQ / 64, 8 * NHEAD), 128, ATT_SMEM>>>(qkh, ah);

    // 3) out-proj + residual(X) -> tmp fp32
    gemm_mma<1><<<dim3(DMODEL / BN, M_ROWS / BM), 256, GEMM_SMEM>>>(
        ah, woh, b_out, X, tmp, nullptr, DMODEL, DMODEL);

    // 4) LN1 -> x1 fp32 + fp16
    ln_kernel<1><<<M_ROWS, 256>>>(tmp, ln1_g, ln1_b, x1, ah);

    // 5) FF1 + GELU -> fp16
    gemm_mma<2><<<dim3(DFF / BN, M_ROWS / BM), 256, GEMM_SMEM>>>(
        ah, w1h, b_ff1, nullptr, nullptr, fh, DFF, DMODEL);

    // 6) FF2 + residual(x1) -> tmp fp32
    gemm_mma<1><<<dim3(DMODEL / BN, M_ROWS / BM), 256, GEMM_SMEM>>>(
        fh, w2h, b_ff2, x1, tmp, nullptr, DMODEL, DFF);

    // 7) LN2 -> out
    ln_kernel<0><<<M_ROWS, 256>>>(tmp, ln2_g, ln2_b, out, nullptr);
}

// round 15
// speedup vs baseline: 2.6231x; 1.2586x over previous
#include <cuda_runtime.h>
#include <cuda_fp16.h>
#include <math.h>
#include <stdint.h>

// ----------------------------------------------------------------------------
// Problem constants: B=8, T=1024, D=1024, H=16, HD=64.  M = B*T = 8192.
// ----------------------------------------------------------------------------
#define M_ROWS 8192
#define DMODEL 1024
#define D3     3072
#define DFF    4096
#define NHEAD  16
#define HDIM   64
#define SEQ    1024

// ----------------------------------------------------------------------------
// Scratch (device globals -- no cudaMalloc allowed)
// ----------------------------------------------------------------------------
__device__ __half g_qkv_h[M_ROWS * D3];       // QKV fp16
__device__ float g_tmp[M_ROWS * DMODEL];      // fp32 pre-LN buffers
__device__ float g_x1 [M_ROWS * DMODEL];
__device__ __half g_act_h[M_ROWS * DMODEL];   // activation fp16 (X / ctx / x1)
__device__ __half g_ffh_h[M_ROWS * DFF];      // FF1 out fp16
// weights, transposed to [N,K], fp16
__device__ __half g_wqkv_h[DMODEL * D3];
__device__ __half g_wout_h[DMODEL * DMODEL];
__device__ __half g_wff1_h[DMODEL * DFF];
__device__ __half g_wff2_h[DFF * DMODEL];

// ----------------------------------------------------------------------------
// PTX helpers (compute_103-baseline legal: cp.async / ldmatrix / mma.sync)
// ----------------------------------------------------------------------------
__device__ __forceinline__ uint32_t smem_to_u32(const void* smem_ptr) {
    uint32_t addr;
    asm("{ .reg .u64 tmp; cvta.to.shared.u64 tmp, %1; cvt.u32.u64 %0, tmp; }"
        : "=r"(addr) : "l"(smem_ptr));
    return addr;
}

__device__ __forceinline__ void cp16(uint32_t smem_addr, const void* gptr) {
    asm volatile("cp.async.cg.shared.global [%0], [%1], 16;"
                 :: "r"(smem_addr), "l"(gptr));
}
#define CP_COMMIT() asm volatile("cp.async.commit_group;" ::: "memory")
#define CP_WAIT1()  asm volatile("cp.async.wait_group 1;" ::: "memory")

__device__ __forceinline__ void ldsm4(uint32_t* d, uint32_t addr) {
    asm volatile("ldmatrix.sync.aligned.m8n8.x4.shared.b16 {%0,%1,%2,%3}, [%4];"
        : "=r"(d[0]), "=r"(d[1]), "=r"(d[2]), "=r"(d[3]) : "r"(addr));
}
__device__ __forceinline__ void ldsm2(uint32_t* d, uint32_t addr) {
    asm volatile("ldmatrix.sync.aligned.m8n8.x2.shared.b16 {%0,%1}, [%2];"
        : "=r"(d[0]), "=r"(d[1]) : "r"(addr));
}
__device__ __forceinline__ void ldsm2t(uint32_t* d, uint32_t addr) {
    asm volatile("ldmatrix.sync.aligned.m8n8.x2.trans.shared.b16 {%0,%1}, [%2];"
        : "=r"(d[0]), "=r"(d[1]) : "r"(addr));
}

__device__ __forceinline__ void mma16816(float* c, const uint32_t* a, const uint32_t* b) {
    asm volatile("mma.sync.aligned.m16n8k16.row.col.f32.f16.f16.f32 "
        "{%0,%1,%2,%3}, {%4,%5,%6,%7}, {%8,%9}, {%0,%1,%2,%3};"
        : "+f"(c[0]), "+f"(c[1]), "+f"(c[2]), "+f"(c[3])
        : "r"(a[0]), "r"(a[1]), "r"(a[2]), "r"(a[3]), "r"(b[0]), "r"(b[1]));
}

__device__ __forceinline__ uint32_t pack2h(float a, float b) {
    __half2 hp(__float2half(a), __float2half(b));
    return *(uint32_t*)&hp;
}

__global__ __launch_bounds__(256) void convert_h_kernel(
    const float* __restrict__ x, __half* __restrict__ h, int n4)
{
    int i = blockIdx.x * 256 + threadIdx.x;
    if (i >= n4) return;
    float4 v = ((const float4*)x)[i];
    ((uint2*)h)[i] = make_uint2(pack2h(v.x, v.y), pack2h(v.z, v.w));
}

// ----------------------------------------------------------------------------
// Fused weight transpose: all four W [K,N] fp32 -> Wt [N,K] fp16 in ONE launch.
// Flat tile grid: qkv 3072 | out 1024 | ff1 4096 | ff2 4096 = 12288 tiles.
// ----------------------------------------------------------------------------
__global__ __launch_bounds__(256) void transpose_all_kernel(
    const float* __restrict__ Wq, const float* __restrict__ Wo,
    const float* __restrict__ W1, const float* __restrict__ W2,
    __half* __restrict__ Hq, __half* __restrict__ Ho,
    __half* __restrict__ H1, __half* __restrict__ H2)
{
    const int t = blockIdx.x;
    const float* W; __half* H; int K, N, nx, loc;
    if (t < 3072)      { W = Wq; H = Hq; K = DMODEL; N = D3;     nx = 96;  loc = t; }
    else if (t < 4096) { W = Wo; H = Ho; K = DMODEL; N = DMODEL; nx = 32;  loc = t - 3072; }
    else if (t < 8192) { W = W1; H = H1; K = DMODEL; N = DFF;    nx = 128; loc = t - 4096; }
    else               { W = W2; H = H2; K = DFF;    N = DMODEL; nx = 32;  loc = t - 8192; }
    const int n0 = (loc % nx) * 32;
    const int k0 = (loc / nx) * 32;

    __shared__ float tt[32][33];
    const int tx = threadIdx.x & 31;
    const int ty = threadIdx.x >> 5;
    #pragma unroll
    for (int r = 0; r < 4; r++)
        tt[ty * 4 + r][tx] = W[(size_t)(k0 + ty * 4 + r) * N + n0 + tx];
    __syncthreads();
    #pragma unroll
    for (int r = 0; r < 4; r++) {
        int n = n0 + ty * 4 + r;
        H[(size_t)n * K + k0 + tx] = __float2half(tt[tx][ty * 4 + r]);
    }
}

// ----------------------------------------------------------------------------
// Pure-fp16 mma.sync GEMM:  C[M,N] = A[M,K] @ Bt[N,K]^T + bias (+ epilogue)
// Tile 128x128, BK=32, 256 threads (8 warps, each 64x32), 3-stage cp.async,
// 2 CTAs/SM (launch_bounds cap 128 regs; smem 61440 x2 = 123 KB/SM).
// EPI: 1 = bias + residual -> fp32;  2 = bias + exact GELU -> fp16;
//      3 = bias -> fp16
// ----------------------------------------------------------------------------
#define BM 128
#define BN 128
#define BK 32
#define ROWB 80
#define AH_OFF 0
#define BH_OFF 10240
#define STAGE_BYTES 20480
#define GEMM_SMEM (3 * STAGE_BYTES)   // 61440

__device__ __forceinline__ float gelu_exact(float x) {
    return 0.5f * x * (1.0f + erff(x * 0.70710678118654752440f));
}

template <int EPI>
__global__ __launch_bounds__(256, 2) void gemm_mma(
    const __half* __restrict__ Ah, const __half* __restrict__ Bh,
    const float* __restrict__ bias, const float* __restrict__ res,
    float* __restrict__ C, __half* __restrict__ Ch, int N, int K)
{
    extern __shared__ char smem[];
    const uint32_t sbase = smem_to_u32(smem);
    const int tid  = threadIdx.x;
    const int wid  = tid >> 5;
    const int lane = tid & 31;
    const int m0 = blockIdx.y * BM;
    const int n0 = blockIdx.x * BN;

    // loaders: 2 threads/row, 2 chunks each (rows 0..127 for both A and B)
    const int r  = tid >> 1;
    const int c2 = (tid & 1) * 2;

    const int wm = (wid & 1) * 64;
    const int wn = (wid >> 1) * 32;

    float acc[4][4][4];
    #pragma unroll
    for (int i = 0; i < 4; i++)
        #pragma unroll
        for (int j = 0; j < 4; j++)
            #pragma unroll
            for (int k = 0; k < 4; k++) acc[i][j][k] = 0.0f;

    const int KT = K / BK;

    auto load_stage = [&](int it, int s) {
        const int kc = it * BK;
        const uint32_t st = sbase + s * STAGE_BYTES;
        const uint32_t sa = st + r * ROWB + c2 * 16;
        const size_t ga = (size_t)(m0 + r) * K + kc + c2 * 8;
        const size_t gb = (size_t)(n0 + r) * K + kc + c2 * 8;
        cp16(sa + AH_OFF,      Ah + ga);
        cp16(sa + AH_OFF + 16, Ah + ga + 8);
        cp16(sa + BH_OFF,      Bh + gb);
        cp16(sa + BH_OFF + 16, Bh + gb + 8);
    };

    load_stage(0, 0); CP_COMMIT();
    load_stage(1, 1); CP_COMMIT();

    for (int it = 0; it < KT; it++) {
        CP_WAIT1();
        __syncthreads();
        const int nx = it + 2;
        if (nx < KT) load_stage(nx, nx % 3);
        CP_COMMIT();

        const uint32_t st = sbase + (it % 3) * STAGE_BYTES;
        #pragma unroll
        for (int ks = 0; ks < 2; ks++) {
            const int kb  = (ks * 16 + (lane >> 4) * 8) * 2;
            const int kbB = (ks * 16 + ((lane >> 3) & 1) * 8) * 2;
            uint32_t a_h[4][4];
            #pragma unroll
            for (int mf = 0; mf < 4; mf++) {
                uint32_t ra = st + AH_OFF + (wm + mf * 16 + (lane & 15)) * ROWB + kb;
                ldsm4(a_h[mf], ra);
            }
            #pragma unroll
            for (int nf = 0; nf < 4; nf++) {
                uint32_t rb = st + BH_OFF + (wn + nf * 8 + (lane & 7)) * ROWB + kbB;
                uint32_t b_h[2];
                ldsm2(b_h, rb);
                #pragma unroll
                for (int mf = 0; mf < 4; mf++)
                    mma16816(acc[mf][nf], a_h[mf], b_h);
            }
        }
    }

    #pragma unroll
    for (int mf = 0; mf < 4; mf++) {
        const int m = m0 + wm + mf * 16 + (lane >> 2);
        #pragma unroll
        for (int nf = 0; nf < 4; nf++) {
            const int n = n0 + wn + nf * 8 + (lane & 3) * 2;
            float2 bv = *(const float2*)(bias + n);
            float* a = acc[mf][nf];
            float v0 = a[0] + bv.x, v1 = a[1] + bv.y;
            float v2 = a[2] + bv.x, v3 = a[3] + bv.y;
            if (EPI == 1) {
                float2 r0 = *(const float2*)(res + (size_t)m * N + n);
                float2 r1 = *(const float2*)(res + (size_t)(m + 8) * N + n);
                v0 += r0.x; v1 += r0.y; v2 += r1.x; v3 += r1.y;
            }
            if (EPI == 2) {
                v0 = gelu_exact(v0); v1 = gelu_exact(v1);
                v2 = gelu_exact(v2); v3 = gelu_exact(v3);
            }
            if (EPI >= 2) {
                *(uint32_t*)(Ch + (size_t)m * N + n)       = pack2h(v0, v1);
                *(uint32_t*)(Ch + (size_t)(m + 8) * N + n) = pack2h(v2, v3);
            } else {
                *(float2*)(C + (size_t)m * N + n)       = make_float2(v0, v1);
                *(float2*)(C + (size_t)(m + 8) * N + n) = make_float2(v2, v3);
            }
        }
    }
}

// ----------------------------------------------------------------------------
// Tensor-core flash attention (pure fp16 operands, fp32 accum/softmax).
// CTA: 64 q rows x one (b,h); 4 warps x 16 q rows; K tiles of 64 keys.
// ----------------------------------------------------------------------------
#define AROW 144
#define AQ_BYTES (64 * AROW)           // 9216
#define AST (2 * AQ_BYTES)             // Kh,Vh = 18432
#define ATT_SMEM (AQ_BYTES + 2 * AST)  // 46080

__global__ __launch_bounds__(128) void attn_mma(
    const __half* __restrict__ qkv, __half* __restrict__ oh)
{
    extern __shared__ char smem[];
    const uint32_t sb = smem_to_u32(smem);
    const int tid  = threadIdx.x;
    const int w    = tid >> 5;
    const int lane = tid & 31;
    const int bh = blockIdx.y;
    const int b  = bh >> 4;
    const int h  = bh & 15;
    const int q0 = blockIdx.x * 64;

    const uint32_t QHs = sb;
    const int r  = tid >> 1;
    const int cb = (tid & 1) * 4;

    {
        const size_t g = (size_t)(b * SEQ + q0 + r) * D3 + h * HDIM + cb * 8;
        const uint32_t o = r * AROW + cb * 16;
        #pragma unroll
        for (int c = 0; c < 4; c++)
            cp16(QHs + o + c * 16, qkv + g + c * 8);
    }
    auto load_kv = [&](int kt, int s) {
        const uint32_t st = sb + AQ_BYTES + s * AST;
        const size_t gk = (size_t)(b * SEQ + kt * 64 + r) * D3 + DMODEL + h * HDIM + cb * 8;
        const size_t gv = gk + DMODEL;
        const uint32_t o = r * AROW + cb * 16;
        #pragma unroll
        for (int c = 0; c < 4; c++) {
            cp16(st + o + c * 16,            qkv + gk + c * 8);
            cp16(st + AQ_BYTES + o + c * 16, qkv + gv + c * 8);
        }
    };
    load_kv(0, 0); CP_COMMIT();
    load_kv(1, 1); CP_COMMIT();

    uint32_t qfh[4][4];
    float O[8][4];
    #pragma unroll
    for (int i = 0; i < 8; i++)
        #pragma unroll
        for (int j = 0; j < 4; j++) O[i][j] = 0.0f;
    float m0 = -1e30f, m1 = -1e30f, l0 = 0.0f, l1 = 0.0f;

    for (int kt = 0; kt < SEQ / 64; kt++) {
        CP_WAIT1();
        __syncthreads();
        if (kt == 0) {
            #pragma unroll
            for (int kf = 0; kf < 4; kf++) {
                uint32_t qa = QHs + (w * 16 + (lane & 15)) * AROW + kf * 32 + (lane >> 4) * 16;
                ldsm4(qfh[kf], qa);
            }
        }
        const uint32_t st = sb + AQ_BYTES + (kt & 1) * AST;

        float s[8][4];
        #pragma unroll
        for (int i = 0; i < 8; i++)
            #pragma unroll
            for (int j = 0; j < 4; j++) s[i][j] = 0.0f;
        #pragma unroll
        for (int kf = 0; kf < 4; kf++) {
            #pragma unroll
            for (int nf = 0; nf < 8; nf++) {
                uint32_t ka = st + (nf * 8 + (lane & 7)) * AROW + kf * 32 + ((lane >> 3) & 1) * 16;
                uint32_t b_h[2];
                ldsm2(b_h, ka);
                mma16816(s[nf], qfh[kf], b_h);
            }
        }

        float mx0 = -1e30f, mx1 = -1e30f;
        #pragma unroll
        for (int nf = 0; nf < 8; nf++) {
            s[nf][0] *= 0.125f; s[nf][1] *= 0.125f;
            s[nf][2] *= 0.125f; s[nf][3] *= 0.125f;
            mx0 = fmaxf(mx0, fmaxf(s[nf][0], s[nf][1]));
            mx1 = fmaxf(mx1, fmaxf(s[nf][2], s[nf][3]));
        }
        mx0 = fmaxf(mx0, __shfl_xor_sync(0xffffffffu, mx0, 1));
        mx0 = fmaxf(mx0, __shfl_xor_sync(0xffffffffu, mx0, 2));
        mx1 = fmaxf(mx1, __shfl_xor_sync(0xffffffffu, mx1, 1));
        mx1 = fmaxf(mx1, __shfl_xor_sync(0xffffffffu, mx1, 2));
        float mn0 = fmaxf(m0, mx0), mn1 = fmaxf(m1, mx1);
        float cr0 = __expf(m0 - mn0), cr1 = __expf(m1 - mn1);
        float sm0 = 0.0f, sm1 = 0.0f;
        #pragma unroll
        for (int nf = 0; nf < 8; nf++) {
            s[nf][0] = __expf(s[nf][0] - mn0); sm0 += s[nf][0];
            s[nf][1] = __expf(s[nf][1] - mn0); sm0 += s[nf][1];
            s[nf][2] = __expf(s[nf][2] - mn1); sm1 += s[nf][2];
            s[nf][3] = __expf(s[nf][3] - mn1); sm1 += s[nf][3];
        }
        sm0 += __shfl_xor_sync(0xffffffffu, sm0, 1);
        sm0 += __shfl_xor_sync(0xffffffffu, sm0, 2);
        sm1 += __shfl_xor_sync(0xffffffffu, sm1, 1);
        sm1 += __shfl_xor_sync(0xffffffffu, sm1, 2);
        l0 = l0 * cr0 + sm0; m0 = mn0;
        l1 = l1 * cr1 + sm1; m1 = mn1;
        #pragma unroll
        for (int nf = 0; nf < 8; nf++) {
            O[nf][0] *= cr0; O[nf][1] *= cr0;
            O[nf][2] *= cr1; O[nf][3] *= cr1;
        }

        #pragma unroll
        for (int kf = 0; kf < 4; kf++) {
            uint32_t pa[4];
            pa[0] = pack2h(s[2*kf][0],   s[2*kf][1]);
            pa[1] = pack2h(s[2*kf][2],   s[2*kf][3]);
            pa[2] = pack2h(s[2*kf+1][0], s[2*kf+1][1]);
            pa[3] = pack2h(s[2*kf+1][2], s[2*kf+1][3]);
            #pragma unroll
            for (int nf = 0; nf < 8; nf++) {
                uint32_t va = st + AQ_BYTES + (kf * 16 + (lane & 15)) * AROW + nf * 16;
                uint32_t b_h[2];
                ldsm2t(b_h, va);
                mma16816(O[nf], pa, b_h);
            }
        }

        __syncthreads();
        if (kt + 2 < SEQ / 64) load_kv(kt + 2, kt & 1);
        CP_COMMIT();
    }

    {
        float i0 = 1.0f / l0, i1 = 1.0f / l1;
        const int mr = q0 + w * 16 + (lane >> 2);
        const size_t row0 = (size_t)(b * SEQ + mr) * DMODEL;
        const size_t row1 = row0 + 8 * DMODEL;
        #pragma unroll
        for (int nf = 0; nf < 8; nf++) {
            const int n = h * HDIM + nf * 8 + (lane & 3) * 2;
            *(uint32_t*)(oh + row0 + n) = pack2h(O[nf][0] * i0, O[nf][1] * i0);
            *(uint32_t*)(oh + row1 + n) = pack2h(O[nf][2] * i1, O[nf][3] * i1);
        }
    }
}

// ----------------------------------------------------------------------------
// LayerNorm; SPLIT=1 additionally emits fp16 of the output
// ----------------------------------------------------------------------------
template <int SPLIT>
__global__ __launch_bounds__(256) void ln_kernel(
    const float* __restrict__ x, const float* __restrict__ g,
    const float* __restrict__ beta, float* __restrict__ y,
    __half* __restrict__ yh)
{
    const int row = blockIdx.x;
    const int tid = threadIdx.x;
    const float* xr = x + (size_t)row * DMODEL;

    float4 v = *(const float4*)(xr + tid * 4);
    float s  = v.x + v.y + v.z + v.w;
    float sq = v.x*v.x + v.y*v.y + v.z*v.z + v.w*v.w;

    #pragma unroll
    for (int off = 16; off > 0; off >>= 1) {
        s  += __shfl_xor_sync(0xffffffffu, s,  off);
        sq += __shfl_xor_sync(0xffffffffu, sq, off);
    }
    __shared__ float ss[8], ssq[8];
    if ((tid & 31) == 0) { ss[tid >> 5] = s; ssq[tid >> 5] = sq; }
    __syncthreads();
    float tot = 0.0f, totq = 0.0f;
    #pragma unroll
    for (int i = 0; i < 8; i++) { tot += ss[i]; totq += ssq[i]; }

    const float mu   = tot * (1.0f / DMODEL);
    const float var  = totq * (1.0f / DMODEL) - mu * mu;
    const float rstd = rsqrtf(var + 1e-5f);

    float4 gg = *(const float4*)(g + tid * 4);
    float4 bb = *(const float4*)(beta + tid * 4);
    float4 o;
    o.x = (v.x - mu) * rstd * gg.x + bb.x;
    o.y = (v.y - mu) * rstd * gg.y + bb.y;
    o.z = (v.z - mu) * rstd * gg.z + bb.z;
    o.w = (v.w - mu) * rstd * gg.w + bb.w;
    *(float4*)(y + (size_t)row * DMODEL + tid * 4) = o;

    if (SPLIT) {
        ((uint2*)(yh + (size_t)row * DMODEL))[tid] =
            make_uint2(pack2h(o.x, o.y), pack2h(o.z, o.w));
    }
}

// ----------------------------------------------------------------------------
// kernel_launch
// Inputs: 0 X, 1 W_qkv, 2 b_qkv, 3 W_out, 4 b_out, 5 ln1_g, 6 ln1_b,
//         7 ln2_g, 8 ln2_b, 9 W_ff1, 10 b_ff1, 11 W_ff2, 12 b_ff2
// ----------------------------------------------------------------------------
extern "C" void kernel_launch(void* const* d_in, const int* in_sizes, int n_in,
                              void* d_out, int out_size)
{
    const float* X      = (const float*)d_in[0];
    const float* W_qkv  = (const float*)d_in[1];
    const float* b_qkv  = (const float*)d_in[2];
    const float* W_out  = (const float*)d_in[3];
    const float* b_out  = (const float*)d_in[4];
    const float* ln1_g  = (const float*)d_in[5];
    const float* ln1_b  = (const float*)d_in[6];
    const float* ln2_g  = (const float*)d_in[7];
    const float* ln2_b  = (const float*)d_in[8];
    const float* W_ff1  = (const float*)d_in[9];
    const float* b_ff1  = (const float*)d_in[10];
    const float* W_ff2  = (const float*)d_in[11];
    const float* b_ff2  = (const float*)d_in[12];
    float* out = (float*)d_out;

    float *tmp, *x1;
    __half *qkh, *ah, *fh;
    __half *wqh, *woh, *w1h, *w2h;
    cudaGetSymbolAddress((void**)&qkh, g_qkv_h);
    cudaGetSymbolAddress((void**)&tmp, g_tmp);
    cudaGetSymbolAddress((void**)&x1,  g_x1);
    cudaGetSymbolAddress((void**)&ah,  g_act_h);
    cudaGetSymbolAddress((void**)&fh,  g_ffh_h);
    cudaGetSymbolAddress((void**)&wqh, g_wqkv_h);
    cudaGetSymbolAddress((void**)&woh, g_wout_h);
    cudaGetSymbolAddress((void**)&w1h, g_wff1_h);
    cudaGetSymbolAddress((void**)&w2h, g_wff2_h);

    cudaFuncSetAttribute(gemm_mma<1>, cudaFuncAttributeMaxDynamicSharedMemorySize, GEMM_SMEM);
    cudaFuncSetAttribute(gemm_mma<2>, cudaFuncAttributeMaxDynamicSharedMemorySize, GEMM_SMEM);
    cudaFuncSetAttribute(gemm_mma<3>, cudaFuncAttributeMaxDynamicSharedMemorySize, GEMM_SMEM);
    cudaFuncSetAttribute(attn_mma, cudaFuncAttributeMaxDynamicSharedMemorySize, ATT_SMEM);

    // 0) fused weight transposes -> [N,K] fp16 (one launch)
    transpose_all_kernel<<<12288, 256>>>(W_qkv, W_out, W_ff1, W_ff2,
                                         wqh, woh, w1h, w2h);

    // 1) convert X -> fp16; QKV projection -> fp16
    convert_h_kernel<<<(M_ROWS * DMODEL / 4) / 256, 256>>>(X, ah, M_ROWS * DMODEL / 4);
    gemm_mma<3><<<dim3(D3 / BN, M_ROWS / BM), 256, GEMM_SMEM>>>(
        ah, wqh, b_qkv, nullptr, nullptr, qkh, D3, DMODEL);

    // 2) tensor-core attention -> ctx fp16 (reuses act buffer)
    attn_mma<<<dim3(SEQ / 64, 8 * NHEAD), 128, ATT_SMEM>>>(qkh, ah);

    // 3) out-proj + residual(X) -> tmp fp32
    gemm_mma<1><<<dim3(DMODEL / BN, M_ROWS / BM), 256, GEMM_SMEM>>>(
        ah, woh, b_out, X, tmp, nullptr, DMODEL, DMODEL);

    // 4) LN1 -> x1 fp32 + fp16
    ln_kernel<1><<<M_ROWS, 256>>>(tmp, ln1_g, ln1_b, x1, ah);

    // 5) FF1 + GELU -> fp16
    gemm_mma<2><<<dim3(DFF / BN, M_ROWS / BM), 256, GEMM_SMEM>>>(
        ah, w1h, b_ff1, nullptr, nullptr, fh, DFF, DMODEL);

    // 6) FF2 + residual(x1) -> tmp fp32
    gemm_mma<1><<<dim3(DMODEL / BN, M_ROWS / BM), 256, GEMM_SMEM>>>(
        fh, w2h, b_ff2, x1, tmp, nullptr, DMODEL, DFF);

    // 7) LN2 -> out
    ln_kernel<0><<<M_ROWS, 256>>>(tmp, ln2_g, ln2_b, out, nullptr);
}

// round 16
// speedup vs baseline: 2.7180x; 1.0362x over previous
#include <cuda_runtime.h>
#include <cuda_fp16.h>
#include <math.h>
#include <stdint.h>

// ----------------------------------------------------------------------------
// Problem constants: B=8, T=1024, D=1024, H=16, HD=64.  M = B*T = 8192.
// ----------------------------------------------------------------------------
#define M_ROWS 8192
#define DMODEL 1024
#define D3     3072
#define DFF    4096
#define NHEAD  16
#define HDIM   64
#define SEQ    1024

// ----------------------------------------------------------------------------
// Scratch (device globals -- no cudaMalloc allowed)
// ----------------------------------------------------------------------------
__device__ __half g_qkv_h[M_ROWS * D3];       // QKV fp16
__device__ float g_tmp[M_ROWS * DMODEL];      // fp32 pre-LN buffers
__device__ float g_x1 [M_ROWS * DMODEL];
__device__ __half g_act_h[M_ROWS * DMODEL];   // activation fp16 (X / ctx / x1)
__device__ __half g_ffh_h[M_ROWS * DFF];      // FF1 out fp16
// weights, transposed to [N,K], fp16
__device__ __half g_wqkv_h[DMODEL * D3];
__device__ __half g_wout_h[DMODEL * DMODEL];
__device__ __half g_wff1_h[DMODEL * DFF];
__device__ __half g_wff2_h[DFF * DMODEL];

// ----------------------------------------------------------------------------
// PTX helpers (compute_103-baseline legal: cp.async / ldmatrix / mma.sync)
// ----------------------------------------------------------------------------
__device__ __forceinline__ uint32_t smem_to_u32(const void* smem_ptr) {
    uint32_t addr;
    asm("{ .reg .u64 tmp; cvta.to.shared.u64 tmp, %1; cvt.u32.u64 %0, tmp; }"
        : "=r"(addr) : "l"(smem_ptr));
    return addr;
}

__device__ __forceinline__ void cp16(uint32_t smem_addr, const void* gptr) {
    asm volatile("cp.async.cg.shared.global [%0], [%1], 16;"
                 :: "r"(smem_addr), "l"(gptr));
}
#define CP_COMMIT() asm volatile("cp.async.commit_group;" ::: "memory")
#define CP_WAIT1()  asm volatile("cp.async.wait_group 1;" ::: "memory")
#define CP_WAIT2()  asm volatile("cp.async.wait_group 2;" ::: "memory")

__device__ __forceinline__ void ldsm4(uint32_t* d, uint32_t addr) {
    asm volatile("ldmatrix.sync.aligned.m8n8.x4.shared.b16 {%0,%1,%2,%3}, [%4];"
        : "=r"(d[0]), "=r"(d[1]), "=r"(d[2]), "=r"(d[3]) : "r"(addr));
}
__device__ __forceinline__ void ldsm2(uint32_t* d, uint32_t addr) {
    asm volatile("ldmatrix.sync.aligned.m8n8.x2.shared.b16 {%0,%1}, [%2];"
        : "=r"(d[0]), "=r"(d[1]) : "r"(addr));
}
__device__ __forceinline__ void ldsm2t(uint32_t* d, uint32_t addr) {
    asm volatile("ldmatrix.sync.aligned.m8n8.x2.trans.shared.b16 {%0,%1}, [%2];"
        : "=r"(d[0]), "=r"(d[1]) : "r"(addr));
}

__device__ __forceinline__ void mma16816(float* c, const uint32_t* a, const uint32_t* b) {
    asm volatile("mma.sync.aligned.m16n8k16.row.col.f32.f16.f16.f32 "
        "{%0,%1,%2,%3}, {%4,%5,%6,%7}, {%8,%9}, {%0,%1,%2,%3};"
        : "+f"(c[0]), "+f"(c[1]), "+f"(c[2]), "+f"(c[3])
        : "r"(a[0]), "r"(a[1]), "r"(a[2]), "r"(a[3]), "r"(b[0]), "r"(b[1]));
}

__device__ __forceinline__ uint32_t pack2h(float a, float b) {
    __half2 hp(__float2half(a), __float2half(b));
    return *(uint32_t*)&hp;
}

// ----------------------------------------------------------------------------
// Fused prep: four weight transposes [K,N]fp32 -> [N,K]fp16 PLUS X fp32->fp16.
// Flat grid: qkv 3072 | out 1024 | ff1 4096 | ff2 4096 | X-convert 8192.
// ----------------------------------------------------------------------------
#define PREP_TILES 12288
#define CONV_BLOCKS 8192   // (8192*1024/4)/256

__global__ __launch_bounds__(256) void prep_kernel(
    const float* __restrict__ Wq, const float* __restrict__ Wo,
    const float* __restrict__ W1, const float* __restrict__ W2,
    const float* __restrict__ X,
    __half* __restrict__ Hq, __half* __restrict__ Ho,
    __half* __restrict__ H1, __half* __restrict__ H2,
    __half* __restrict__ Xh)
{
    const int t = blockIdx.x;
    if (t >= PREP_TILES) {
        const int i = (t - PREP_TILES) * 256 + threadIdx.x;
        float4 v = ((const float4*)X)[i];
        ((uint2*)Xh)[i] = make_uint2(pack2h(v.x, v.y), pack2h(v.z, v.w));
        return;
    }
    const float* W; __half* H; int K, N, nx, loc;
    if (t < 3072)      { W = Wq; H = Hq; K = DMODEL; N = D3;     nx = 96;  loc = t; }
    else if (t < 4096) { W = Wo; H = Ho; K = DMODEL; N = DMODEL; nx = 32;  loc = t - 3072; }
    else if (t < 8192) { W = W1; H = H1; K = DMODEL; N = DFF;    nx = 128; loc = t - 4096; }
    else               { W = W2; H = H2; K = DFF;    N = DMODEL; nx = 32;  loc = t - 8192; }
    const int n0 = (loc % nx) * 32;
    const int k0 = (loc / nx) * 32;

    __shared__ float tt[32][33];
    const int tx = threadIdx.x & 31;
    const int ty = threadIdx.x >> 5;
    #pragma unroll
    for (int r = 0; r < 4; r++)
        tt[ty * 4 + r][tx] = W[(size_t)(k0 + ty * 4 + r) * N + n0 + tx];
    __syncthreads();
    #pragma unroll
    for (int r = 0; r < 4; r++) {
        int n = n0 + ty * 4 + r;
        H[(size_t)n * K + k0 + tx] = __float2half(tt[tx][ty * 4 + r]);
    }
}

// ----------------------------------------------------------------------------
// Pure-fp16 mma.sync GEMM:  C[M,N] = A[M,K] @ Bt[N,K]^T + bias (+ epilogue)
// Tile 128x128, BK=32, 256 threads (8 warps, each 64x32), 4-stage cp.async,
// 2 CTAs/SM.
// EPI: 1 = bias + residual -> fp32;  2 = bias + exact GELU -> fp16;
//      3 = bias -> fp16
// ----------------------------------------------------------------------------
#define BM 128
#define BN 128
#define BK 32
#define ROWB 80
#define AH_OFF 0
#define BH_OFF 10240
#define STAGE_BYTES 20480
#define NSTAGE 4
#define GEMM_SMEM (NSTAGE * STAGE_BYTES)   // 81920

__device__ __forceinline__ float gelu_exact(float x) {
    return 0.5f * x * (1.0f + erff(x * 0.70710678118654752440f));
}

template <int EPI>
__global__ __launch_bounds__(256, 2) void gemm_mma(
    const __half* __restrict__ Ah, const __half* __restrict__ Bh,
    const float* __restrict__ bias, const float* __restrict__ res,
    float* __restrict__ C, __half* __restrict__ Ch, int N, int K)
{
    extern __shared__ char smem[];
    const uint32_t sbase = smem_to_u32(smem);
    const int tid  = threadIdx.x;
    const int wid  = tid >> 5;
    const int lane = tid & 31;
    const int m0 = blockIdx.y * BM;
    const int n0 = blockIdx.x * BN;

    const int r  = tid >> 1;
    const int c2 = (tid & 1) * 2;

    const int wm = (wid & 1) * 64;
    const int wn = (wid >> 1) * 32;

    float acc[4][4][4];
    #pragma unroll
    for (int i = 0; i < 4; i++)
        #pragma unroll
        for (int j = 0; j < 4; j++)
            #pragma unroll
            for (int k = 0; k < 4; k++) acc[i][j][k] = 0.0f;

    const int KT = K / BK;

    auto load_stage = [&](int it, int s) {
        const int kc = it * BK;
        const uint32_t st = sbase + s * STAGE_BYTES;
        const uint32_t sa = st + r * ROWB + c2 * 16;
        const size_t ga = (size_t)(m0 + r) * K + kc + c2 * 8;
        const size_t gb = (size_t)(n0 + r) * K + kc + c2 * 8;
        cp16(sa + AH_OFF,      Ah + ga);
        cp16(sa + AH_OFF + 16, Ah + ga + 8);
        cp16(sa + BH_OFF,      Bh + gb);
        cp16(sa + BH_OFF + 16, Bh + gb + 8);
    };

    load_stage(0, 0); CP_COMMIT();
    load_stage(1, 1); CP_COMMIT();
    load_stage(2, 2); CP_COMMIT();

    for (int it = 0; it < KT; it++) {
        CP_WAIT2();
        __syncthreads();
        const int nx = it + 3;
        if (nx < KT) load_stage(nx, nx & (NSTAGE - 1));
        CP_COMMIT();

        const uint32_t st = sbase + (it & (NSTAGE - 1)) * STAGE_BYTES;
        #pragma unroll
        for (int ks = 0; ks < 2; ks++) {
            const int kb  = (ks * 16 + (lane >> 4) * 8) * 2;
            const int kbB = (ks * 16 + ((lane >> 3) & 1) * 8) * 2;
            uint32_t a_h[4][4];
            #pragma unroll
            for (int mf = 0; mf < 4; mf++) {
                uint32_t ra = st + AH_OFF + (wm + mf * 16 + (lane & 15)) * ROWB + kb;
                ldsm4(a_h[mf], ra);
            }
            #pragma unroll
            for (int nf = 0; nf < 4; nf++) {
                uint32_t rb = st + BH_OFF + (wn + nf * 8 + (lane & 7)) * ROWB + kbB;
                uint32_t b_h[2];
                ldsm2(b_h, rb);
                #pragma unroll
                for (int mf = 0; mf < 4; mf++)
                    mma16816(acc[mf][nf], a_h[mf], b_h);
            }
        }
    }

    #pragma unroll
    for (int mf = 0; mf < 4; mf++) {
        const int m = m0 + wm + mf * 16 + (lane >> 2);
        #pragma unroll
        for (int nf = 0; nf < 4; nf++) {
            const int n = n0 + wn + nf * 8 + (lane & 3) * 2;
            float2 bv = *(const float2*)(bias + n);
            float* a = acc[mf][nf];
            float v0 = a[0] + bv.x, v1 = a[1] + bv.y;
            float v2 = a[2] + bv.x, v3 = a[3] + bv.y;
            if (EPI == 1) {
                float2 r0 = *(const float2*)(res + (size_t)m * N + n);
                float2 r1 = *(const float2*)(res + (size_t)(m + 8) * N + n);
                v0 += r0.x; v1 += r0.y; v2 += r1.x; v3 += r1.y;
            }
            if (EPI == 2) {
                v0 = gelu_exact(v0); v1 = gelu_exact(v1);
                v2 = gelu_exact(v2); v3 = gelu_exact(v3);
            }
            if (EPI >= 2) {
                *(uint32_t*)(Ch + (size_t)m * N + n)       = pack2h(v0, v1);
                *(uint32_t*)(Ch + (size_t)(m + 8) * N + n) = pack2h(v2, v3);
            } else {
                *(float2*)(C + (size_t)m * N + n)       = make_float2(v0, v1);
                *(float2*)(C + (size_t)(m + 8) * N + n) = make_float2(v2, v3);
            }
        }
    }
}

// ----------------------------------------------------------------------------
// Tensor-core flash attention (pure fp16 operands, fp32 accum/softmax).
// CTA: 128 q rows x one (b,h); 8 warps x 16 q rows; K tiles of 64 keys;
// 3-stage KV pipeline (prefetch distance 2). KV tile shared by 128 queries.
// ----------------------------------------------------------------------------
#define AROW 144
#define AQ_BYTES (128 * AROW)          // 18432 (Q: 128 rows)
#define KV_TILE (64 * AROW)            // 9216
#define AST (2 * KV_TILE)              // K+V stage = 18432
#define ATT_NSTAGE 3
#define ATT_SMEM (AQ_BYTES + ATT_NSTAGE * AST)  // 73728

__global__ __launch_bounds__(256, 2) void attn_mma(
    const __half* __restrict__ qkv, __half* __restrict__ oh)
{
    extern __shared__ char smem[];
    const uint32_t sb = smem_to_u32(smem);
    const int tid  = threadIdx.x;
    const int w    = tid >> 5;
    const int lane = tid & 31;
    const int bh = blockIdx.y;
    const int b  = bh >> 4;
    const int h  = bh & 15;
    const int q0 = blockIdx.x * 128;

    const uint32_t QHs = sb;

    // Q load: 128 rows, 2 threads/row, 4 chunks each
    {
        const int r  = tid >> 1;
        const int cb = (tid & 1) * 4;
        const size_t g = (size_t)(b * SEQ + q0 + r) * D3 + h * HDIM + cb * 8;
        const uint32_t o = r * AROW + cb * 16;
        #pragma unroll
        for (int c = 0; c < 4; c++)
            cp16(QHs + o + c * 16, qkv + g + c * 8);
    }
    // KV load: threads 0..127 -> K tile, threads 128..255 -> V tile
    auto load_kv = [&](int kt, int s) {
        const uint32_t st = sb + AQ_BYTES + s * AST + (tid >> 7) * KV_TILE;
        const int t2 = tid & 127;
        const int r  = t2 >> 1;
        const int cb = (t2 & 1) * 4;
        const size_t g = (size_t)(b * SEQ + kt * 64 + r) * D3 + DMODEL
                       + (tid >> 7) * DMODEL + h * HDIM + cb * 8;
        const uint32_t o = r * AROW + cb * 16;
        #pragma unroll
        for (int c = 0; c < 4; c++)
            cp16(st + o + c * 16, qkv + g + c * 8);
    };
    load_kv(0, 0); CP_COMMIT();
    load_kv(1, 1); CP_COMMIT();

    uint32_t qfh[4][4];
    float O[8][4];
    #pragma unroll
    for (int i = 0; i < 8; i++)
        #pragma unroll
        for (int j = 0; j < 4; j++) O[i][j] = 0.0f;
    float m0 = -1e30f, m1 = -1e30f, l0 = 0.0f, l1 = 0.0f;

    for (int kt = 0; kt < SEQ / 64; kt++) {
        CP_WAIT1();
        __syncthreads();
        if (kt == 0) {
            #pragma unroll
            for (int kf = 0; kf < 4; kf++) {
                uint32_t qa = QHs + (w * 16 + (lane & 15)) * AROW + kf * 32 + (lane >> 4) * 16;
                ldsm4(qfh[kf], qa);
            }
        }
        const uint32_t st = sb + AQ_BYTES + (kt % ATT_NSTAGE) * AST;

        // ---- S = Q K^T ----
        float s[8][4];
        #pragma unroll
        for (int i = 0; i < 8; i++)
            #pragma unroll
            for (int j = 0; j < 4; j++) s[i][j] = 0.0f;
        #pragma unroll
        for (int kf = 0; kf < 4; kf++) {
            #pragma unroll
            for (int nf = 0; nf < 8; nf++) {
                uint32_t ka = st + (nf * 8 + (lane & 7)) * AROW + kf * 32 + ((lane >> 3) & 1) * 16;
                uint32_t b_h[2];
                ldsm2(b_h, ka);
                mma16816(s[nf], qfh[kf], b_h);
            }
        }

        // ---- online softmax ----
        float mx0 = -1e30f, mx1 = -1e30f;
        #pragma unroll
        for (int nf = 0; nf < 8; nf++) {
            s[nf][0] *= 0.125f; s[nf][1] *= 0.125f;
            s[nf][2] *= 0.125f; s[nf][3] *= 0.125f;
            mx0 = fmaxf(mx0, fmaxf(s[nf][0], s[nf][1]));
            mx1 = fmaxf(mx1, fmaxf(s[nf][2], s[nf][3]));
        }
        mx0 = fmaxf(mx0, __shfl_xor_sync(0xffffffffu, mx0, 1));
        mx0 = fmaxf(mx0, __shfl_xor_sync(0xffffffffu, mx0, 2));
        mx1 = fmaxf(mx1, __shfl_xor_sync(0xffffffffu, mx1, 1));
        mx1 = fmaxf(mx1, __shfl_xor_sync(0xffffffffu, mx1, 2));
        float mn0 = fmaxf(m0, mx0), mn1 = fmaxf(m1, mx1);
        float cr0 = __expf(m0 - mn0), cr1 = __expf(m1 - mn1);
        float sm0 = 0.0f, sm1 = 0.0f;
        #pragma unroll
        for (int nf = 0; nf < 8; nf++) {
            s[nf][0] = __expf(s[nf][0] - mn0); sm0 += s[nf][0];
            s[nf][1] = __expf(s[nf][1] - mn0); sm0 += s[nf][1];
            s[nf][2] = __expf(s[nf][2] - mn1); sm1 += s[nf][2];
            s[nf][3] = __expf(s[nf][3] - mn1); sm1 += s[nf][3];
        }
        sm0 += __shfl_xor_sync(0xffffffffu, sm0, 1);
        sm0 += __shfl_xor_sync(0xffffffffu, sm0, 2);
        sm1 += __shfl_xor_sync(0xffffffffu, sm1, 1);
        sm1 += __shfl_xor_sync(0xffffffffu, sm1, 2);
        l0 = l0 * cr0 + sm0; m0 = mn0;
        l1 = l1 * cr1 + sm1; m1 = mn1;
        #pragma unroll
        for (int nf = 0; nf < 8; nf++) {
            O[nf][0] *= cr0; O[nf][1] *= cr0;
            O[nf][2] *= cr1; O[nf][3] *= cr1;
        }

        // ---- O += P V ----
        #pragma unroll
        for (int kf = 0; kf < 4; kf++) {
            uint32_t pa[4];
            pa[0] = pack2h(s[2*kf][0],   s[2*kf][1]);
            pa[1] = pack2h(s[2*kf][2],   s[2*kf][3]);
            pa[2] = pack2h(s[2*kf+1][0], s[2*kf+1][1]);
            pa[3] = pack2h(s[2*kf+1][2], s[2*kf+1][3]);
            #pragma unroll
            for (int nf = 0; nf < 8; nf++) {
                uint32_t va = st + KV_TILE + (kf * 16 + (lane & 15)) * AROW + nf * 16;
                uint32_t b_h[2];
                ldsm2t(b_h, va);
                mma16816(O[nf], pa, b_h);
            }
        }

        __syncthreads();
        if (kt + 2 < SEQ / 64) load_kv(kt + 2, (kt + 2) % ATT_NSTAGE);
        CP_COMMIT();
    }

    // ---- write ctx fp16 ----
    {
        float i0 = 1.0f / l0, i1 = 1.0f / l1;
        const int mr = q0 + w * 16 + (lane >> 2);
        const size_t row0 = (size_t)(b * SEQ + mr) * DMODEL;
        const size_t row1 = row0 + 8 * DMODEL;
        #pragma unroll
        for (int nf = 0; nf < 8; nf++) {
            const int n = h * HDIM + nf * 8 + (lane & 3) * 2;
            *(uint32_t*)(oh + row0 + n) = pack2h(O[nf][0] * i0, O[nf][1] * i0);
            *(uint32_t*)(oh + row1 + n) = pack2h(O[nf][2] * i1, O[nf][3] * i1);
        }
    }
}

// ----------------------------------------------------------------------------
// LayerNorm; SPLIT=1 additionally emits fp16 of the output
// ----------------------------------------------------------------------------
template <int SPLIT>
__global__ __launch_bounds__(256) void ln_kernel(
    const float* __restrict__ x, const float* __restrict__ g,
    const float* __restrict__ beta, float* __restrict__ y,
    __half* __restrict__ yh)
{
    const int row = blockIdx.x;
    const int tid = threadIdx.x;
    const float* xr = x + (size_t)row * DMODEL;

    float4 v = *(const float4*)(xr + tid * 4);
    float s  = v.x + v.y + v.z + v.w;
    float sq = v.x*v.x + v.y*v.y + v.z*v.z + v.w*v.w;

    #pragma unroll
    for (int off = 16; off > 0; off >>= 1) {
        s  += __shfl_xor_sync(0xffffffffu, s,  off);
        sq += __shfl_xor_sync(0xffffffffu, sq, off);
    }
    __shared__ float ss[8], ssq[8];
    if ((tid & 31) == 0) { ss[tid >> 5] = s; ssq[tid >> 5] = sq; }
    __syncthreads();
    float tot = 0.0f, totq = 0.0f;
    #pragma unroll
    for (int i = 0; i < 8; i++) { tot += ss[i]; totq += ssq[i]; }

    const float mu   = tot * (1.0f / DMODEL);
    const float var  = totq * (1.0f / DMODEL) - mu * mu;
    const float rstd = rsqrtf(var + 1e-5f);

    float4 gg = *(const float4*)(g + tid * 4);
    float4 bb = *(const float4*)(beta + tid * 4);
    float4 o;
    o.x = (v.x - mu) * rstd * gg.x + bb.x;
    o.y = (v.y - mu) * rstd * gg.y + bb.y;
    o.z = (v.z - mu) * rstd * gg.z + bb.z;
    o.w = (v.w - mu) * rstd * gg.w + bb.w;
    *(float4*)(y + (size_t)row * DMODEL + tid * 4) = o;

    if (SPLIT) {
        ((uint2*)(yh + (size_t)row * DMODEL))[tid] =
            make_uint2(pack2h(o.x, o.y), pack2h(o.z, o.w));
    }
}

// ----------------------------------------------------------------------------
// kernel_launch
// Inputs: 0 X, 1 W_qkv, 2 b_qkv, 3 W_out, 4 b_out, 5 ln1_g, 6 ln1_b,
//         7 ln2_g, 8 ln2_b, 9 W_ff1, 10 b_ff1, 11 W_ff2, 12 b_ff2
// ----------------------------------------------------------------------------
extern "C" void kernel_launch(void* const* d_in, const int* in_sizes, int n_in,
                              void* d_out, int out_size)
{
    const float* X      = (const float*)d_in[0];
    const float* W_qkv  = (const float*)d_in[1];
    const float* b_qkv  = (const float*)d_in[2];
    const float* W_out  = (const float*)d_in[3];
    const float* b_out  = (const float*)d_in[4];
    const float* ln1_g  = (const float*)d_in[5];
    const float* ln1_b  = (const float*)d_in[6];
    const float* ln2_g  = (const float*)d_in[7];
    const float* ln2_b  = (const float*)d_in[8];
    const float* W_ff1  = (const float*)d_in[9];
    const float* b_ff1  = (const float*)d_in[10];
    const float* W_ff2  = (const float*)d_in[11];
    const float* b_ff2  = (const float*)d_in[12];
    float* out = (float*)d_out;

    float *tmp, *x1;
    __half *qkh, *ah, *fh;
    __half *wqh, *woh, *w1h, *w2h;
    cudaGetSymbolAddress((void**)&qkh, g_qkv_h);
    cudaGetSymbolAddress((void**)&tmp, g_tmp);
    cudaGetSymbolAddress((void**)&x1,  g_x1);
    cudaGetSymbolAddress((void**)&ah,  g_act_h);
    cudaGetSymbolAddress((void**)&fh,  g_ffh_h);
    cudaGetSymbolAddress((void**)&wqh, g_wqkv_h);
    cudaGetSymbolAddress((void**)&woh, g_wout_h);
    cudaGetSymbolAddress((void**)&w1h, g_wff1_h);
    cudaGetSymbolAddress((void**)&w2h, g_wff2_h);

    cudaFuncSetAttribute(gemm_mma<1>, cudaFuncAttributeMaxDynamicSharedMemorySize, GEMM_SMEM);
    cudaFuncSetAttribute(gemm_mma<2>, cudaFuncAttributeMaxDynamicSharedMemorySize, GEMM_SMEM);
    cudaFuncSetAttribute(gemm_mma<3>, cudaFuncAttributeMaxDynamicSharedMemorySize, GEMM_SMEM);
    cudaFuncSetAttribute(attn_mma, cudaFuncAttributeMaxDynamicSharedMemorySize, ATT_SMEM);

    // 0) fused weight transposes + X fp16 convert (one launch)
    prep_kernel<<<PREP_TILES + CONV_BLOCKS, 256>>>(
        W_qkv, W_out, W_ff1, W_ff2, X, wqh, woh, w1h, w2h, ah);

    // 1) QKV projection -> fp16
    gemm_mma<3><<<dim3(D3 / BN, M_ROWS / BM), 256, GEMM_SMEM>>>(
        ah, wqh, b_qkv, nullptr, nullptr, qkh, D3, DMODEL);

    // 2) tensor-core attention -> ctx fp16 (reuses act buffer)
    attn_mma<<<dim3(SEQ / 128, 8 * NHEAD), 256, ATT_SMEM>>>(qkh, ah);

    // 3) out-proj + residual(X) -> tmp fp32
    gemm_mma<1><<<dim3(DMODEL / BN, M_ROWS / BM), 256, GEMM_SMEM>>>(
        ah, woh, b_out, X, tmp, nullptr, DMODEL, DMODEL);

    // 4) LN1 -> x1 fp32 + fp16
    ln_kernel<1><<<M_ROWS, 256>>>(tmp, ln1_g, ln1_b, x1, ah);

    // 5) FF1 + GELU -> fp16
    gemm_mma<2><<<dim3(DFF / BN, M_ROWS / BM), 256, GEMM_SMEM>>>(
        ah, w1h, b_ff1, nullptr, nullptr, fh, DFF, DMODEL);

    // 6) FF2 + residual(x1) -> tmp fp32
    gemm_mma<1><<<dim3(DMODEL / BN, M_ROWS / BM), 256, GEMM_SMEM>>>(
        fh, w2h, b_ff2, x1, tmp, nullptr, DMODEL, DFF);

    // 7) LN2 -> out
    ln_kernel<0><<<M_ROWS, 256>>>(tmp, ln2_g, ln2_b, out, nullptr);
}

// round 17
// speedup vs baseline: 2.8704x; 1.0561x over previous
#include <cuda_runtime.h>
#include <cuda_fp16.h>
#include <math.h>
#include <stdint.h>

// ----------------------------------------------------------------------------
// Problem constants: B=8, T=1024, D=1024, H=16, HD=64.  M = B*T = 8192.
// ----------------------------------------------------------------------------
#define M_ROWS 8192
#define DMODEL 1024
#define D3     3072
#define DFF    4096
#define NHEAD  16
#define HDIM   64
#define SEQ    1024

// ----------------------------------------------------------------------------
// Scratch (device globals -- no cudaMalloc allowed)
// ----------------------------------------------------------------------------
__device__ __half g_qkv_h[M_ROWS * D3];       // QKV fp16
__device__ float g_tmp[M_ROWS * DMODEL];      // fp32 pre-LN buffers
__device__ float g_x1 [M_ROWS * DMODEL];
__device__ __half g_act_h[M_ROWS * DMODEL];   // activation fp16 (X / ctx / x1)
__device__ __half g_ffh_h[M_ROWS * DFF];      // FF1 out fp16
// weights, transposed to [N,K], fp16
__device__ __half g_wqkv_h[DMODEL * D3];
__device__ __half g_wout_h[DMODEL * DMODEL];
__device__ __half g_wff1_h[DMODEL * DFF];
__device__ __half g_wff2_h[DFF * DMODEL];

// ----------------------------------------------------------------------------
// PTX helpers (compute_103-baseline legal: cp.async / ldmatrix / mma.sync)
// ----------------------------------------------------------------------------
__device__ __forceinline__ uint32_t smem_to_u32(const void* smem_ptr) {
    uint32_t addr;
    asm("{ .reg .u64 tmp; cvta.to.shared.u64 tmp, %1; cvt.u32.u64 %0, tmp; }"
        : "=r"(addr) : "l"(smem_ptr));
    return addr;
}

__device__ __forceinline__ void cp16(uint32_t smem_addr, const void* gptr) {
    asm volatile("cp.async.cg.shared.global [%0], [%1], 16;"
                 :: "r"(smem_addr), "l"(gptr));
}
#define CP_COMMIT() asm volatile("cp.async.commit_group;" ::: "memory")
#define CP_WAIT1()  asm volatile("cp.async.wait_group 1;" ::: "memory")
#define CP_WAIT2()  asm volatile("cp.async.wait_group 2;" ::: "memory")

__device__ __forceinline__ void ldsm4(uint32_t* d, uint32_t addr) {
    asm volatile("ldmatrix.sync.aligned.m8n8.x4.shared.b16 {%0,%1,%2,%3}, [%4];"
        : "=r"(d[0]), "=r"(d[1]), "=r"(d[2]), "=r"(d[3]) : "r"(addr));
}
__device__ __forceinline__ void ldsm4t(uint32_t* d, uint32_t addr) {
    asm volatile("ldmatrix.sync.aligned.m8n8.x4.trans.shared.b16 {%0,%1,%2,%3}, [%4];"
        : "=r"(d[0]), "=r"(d[1]), "=r"(d[2]), "=r"(d[3]) : "r"(addr));
}

__device__ __forceinline__ void mma16816(float* c, const uint32_t* a, const uint32_t* b) {
    asm volatile("mma.sync.aligned.m16n8k16.row.col.f32.f16.f16.f32 "
        "{%0,%1,%2,%3}, {%4,%5,%6,%7}, {%8,%9}, {%0,%1,%2,%3};"
        : "+f"(c[0]), "+f"(c[1]), "+f"(c[2]), "+f"(c[3])
        : "r"(a[0]), "r"(a[1]), "r"(a[2]), "r"(a[3]), "r"(b[0]), "r"(b[1]));
}

__device__ __forceinline__ uint32_t pack2h(float a, float b) {
    __half2 hp(__float2half(a), __float2half(b));
    return *(uint32_t*)&hp;
}

// ----------------------------------------------------------------------------
// Fused prep: four weight transposes [K,N]fp32 -> [N,K]fp16 PLUS X fp32->fp16.
// Flat grid: qkv 3072 | out 1024 | ff1 4096 | ff2 4096 | X-convert 8192.
// ----------------------------------------------------------------------------
#define PREP_TILES 12288
#define CONV_BLOCKS 8192   // (8192*1024/4)/256

__global__ __launch_bounds__(256) void prep_kernel(
    const float* __restrict__ Wq, const float* __restrict__ Wo,
    const float* __restrict__ W1, const float* __restrict__ W2,
    const float* __restrict__ X,
    __half* __restrict__ Hq, __half* __restrict__ Ho,
    __half* __restrict__ H1, __half* __restrict__ H2,
    __half* __restrict__ Xh)
{
    const int t = blockIdx.x;
    if (t >= PREP_TILES) {
        const int i = (t - PREP_TILES) * 256 + threadIdx.x;
        float4 v = ((const float4*)X)[i];
        ((uint2*)Xh)[i] = make_uint2(pack2h(v.x, v.y), pack2h(v.z, v.w));
        return;
    }
    const float* W; __half* H; int K, N, nx, loc;
    if (t < 3072)      { W = Wq; H = Hq; K = DMODEL; N = D3;     nx = 96;  loc = t; }
    else if (t < 4096) { W = Wo; H = Ho; K = DMODEL; N = DMODEL; nx = 32;  loc = t - 3072; }
    else if (t < 8192) { W = W1; H = H1; K = DMODEL; N = DFF;    nx = 128; loc = t - 4096; }
    else               { W = W2; H = H2; K = DFF;    N = DMODEL; nx = 32;  loc = t - 8192; }
    const int n0 = (loc % nx) * 32;
    const int k0 = (loc / nx) * 32;

    __shared__ float tt[32][33];
    const int tx = threadIdx.x & 31;
    const int ty = threadIdx.x >> 5;
    #pragma unroll
    for (int r = 0; r < 4; r++)
        tt[ty * 4 + r][tx] = W[(size_t)(k0 + ty * 4 + r) * N + n0 + tx];
    __syncthreads();
    #pragma unroll
    for (int r = 0; r < 4; r++) {
        int n = n0 + ty * 4 + r;
        H[(size_t)n * K + k0 + tx] = __float2half(tt[tx][ty * 4 + r]);
    }
}

// ----------------------------------------------------------------------------
// Pure-fp16 mma.sync GEMM:  C[M,N] = A[M,K] @ Bt[N,K]^T + bias (+ epilogue)
// Tile 128x128, BK=32, 256 threads (8 warps, each 64x32), 4-stage cp.async,
// 2 CTAs/SM.  Inner loop: batched ldsm4 frag loads (A x4, B paired x4),
// then an uninterrupted run of 16 MMAs.
// EPI: 1 = bias + residual -> fp32;  2 = bias + exact GELU -> fp16;
//      3 = bias -> fp16
// ----------------------------------------------------------------------------
#define BM 128
#define BN 128
#define BK 32
#define ROWB 80
#define AH_OFF 0
#define BH_OFF 10240
#define STAGE_BYTES 20480
#define NSTAGE 4
#define GEMM_SMEM (NSTAGE * STAGE_BYTES)   // 81920

__device__ __forceinline__ float gelu_exact(float x) {
    return 0.5f * x * (1.0f + erff(x * 0.70710678118654752440f));
}

template <int EPI>
__global__ __launch_bounds__(256, 2) void gemm_mma(
    const __half* __restrict__ Ah, const __half* __restrict__ Bh,
    const float* __restrict__ bias, const float* __restrict__ res,
    float* __restrict__ C, __half* __restrict__ Ch, int N, int K)
{
    extern __shared__ char smem[];
    const uint32_t sbase = smem_to_u32(smem);
    const int tid  = threadIdx.x;
    const int wid  = tid >> 5;
    const int lane = tid & 31;
    const int m0 = blockIdx.y * BM;
    const int n0 = blockIdx.x * BN;

    const int r  = tid >> 1;
    const int c2 = (tid & 1) * 2;

    const int wm = (wid & 1) * 64;
    const int wn = (wid >> 1) * 32;

    float acc[4][4][4];
    #pragma unroll
    for (int i = 0; i < 4; i++)
        #pragma unroll
        for (int j = 0; j < 4; j++)
            #pragma unroll
            for (int k = 0; k < 4; k++) acc[i][j][k] = 0.0f;

    const int KT = K / BK;

    auto load_stage = [&](int it, int s) {
        const int kc = it * BK;
        const uint32_t st = sbase + s * STAGE_BYTES;
        const uint32_t sa = st + r * ROWB + c2 * 16;
        const size_t ga = (size_t)(m0 + r) * K + kc + c2 * 8;
        const size_t gb = (size_t)(n0 + r) * K + kc + c2 * 8;
        cp16(sa + AH_OFF,      Ah + ga);
        cp16(sa + AH_OFF + 16, Ah + ga + 8);
        cp16(sa + BH_OFF,      Bh + gb);
        cp16(sa + BH_OFF + 16, Bh + gb + 8);
    };

    load_stage(0, 0); CP_COMMIT();
    load_stage(1, 1); CP_COMMIT();
    load_stage(2, 2); CP_COMMIT();

    for (int it = 0; it < KT; it++) {
        CP_WAIT2();
        __syncthreads();
        const int nx = it + 3;
        if (nx < KT) load_stage(nx, nx & (NSTAGE - 1));
        CP_COMMIT();

        const uint32_t st = sbase + (it & (NSTAGE - 1)) * STAGE_BYTES;
        #pragma unroll
        for (int ks = 0; ks < 2; ks++) {
            // ---- batched fragment loads ----
            uint32_t a_h[4][4];
            const int kb = ks * 32 + (lane >> 4) * 16;
            #pragma unroll
            for (int mf = 0; mf < 4; mf++) {
                uint32_t ra = st + AH_OFF + (wm + mf * 16 + (lane & 15)) * ROWB + kb;
                ldsm4(a_h[mf], ra);
            }
            uint32_t b_h[4][2];
            const int kbB = ks * 32 + ((lane >> 3) & 1) * 16;
            #pragma unroll
            for (int np = 0; np < 2; np++) {
                uint32_t rb = st + BH_OFF
                    + (wn + (np * 2 + ((lane >> 4) & 1)) * 8 + (lane & 7)) * ROWB + kbB;
                uint32_t d[4];
                ldsm4(d, rb);
                b_h[np * 2][0]     = d[0]; b_h[np * 2][1]     = d[1];
                b_h[np * 2 + 1][0] = d[2]; b_h[np * 2 + 1][1] = d[3];
            }
            // ---- uninterrupted MMA run ----
            #pragma unroll
            for (int nf = 0; nf < 4; nf++)
                #pragma unroll
                for (int mf = 0; mf < 4; mf++)
                    mma16816(acc[mf][nf], a_h[mf], b_h[nf]);
        }
    }

    #pragma unroll
    for (int mf = 0; mf < 4; mf++) {
        const int m = m0 + wm + mf * 16 + (lane >> 2);
        #pragma unroll
        for (int nf = 0; nf < 4; nf++) {
            const int n = n0 + wn + nf * 8 + (lane & 3) * 2;
            float2 bv = *(const float2*)(bias + n);
            float* a = acc[mf][nf];
            float v0 = a[0] + bv.x, v1 = a[1] + bv.y;
            float v2 = a[2] + bv.x, v3 = a[3] + bv.y;
            if (EPI == 1) {
                float2 r0 = *(const float2*)(res + (size_t)m * N + n);
                float2 r1 = *(const float2*)(res + (size_t)(m + 8) * N + n);
                v0 += r0.x; v1 += r0.y; v2 += r1.x; v3 += r1.y;
            }
            if (EPI == 2) {
                v0 = gelu_exact(v0); v1 = gelu_exact(v1);
                v2 = gelu_exact(v2); v3 = gelu_exact(v3);
            }
            if (EPI >= 2) {
                *(uint32_t*)(Ch + (size_t)m * N + n)       = pack2h(v0, v1);
                *(uint32_t*)(Ch + (size_t)(m + 8) * N + n) = pack2h(v2, v3);
            } else {
                *(float2*)(C + (size_t)m * N + n)       = make_float2(v0, v1);
                *(float2*)(C + (size_t)(m + 8) * N + n) = make_float2(v2, v3);
            }
        }
    }
}

// ----------------------------------------------------------------------------
// Tensor-core flash attention (pure fp16 operands, fp32 accum/softmax).
// CTA: 128 q rows x one (b,h); 8 warps x 16 q rows; K tiles of 64 keys;
// 3-stage KV pipeline.  S and PV fragment loads use paired ldsm4/ldsm4t.
// ----------------------------------------------------------------------------
#define AROW 144
#define AQ_BYTES (128 * AROW)          // 18432 (Q: 128 rows)
#define KV_TILE (64 * AROW)            // 9216
#define AST (2 * KV_TILE)              // K+V stage = 18432
#define ATT_NSTAGE 3
#define ATT_SMEM (AQ_BYTES + ATT_NSTAGE * AST)  // 73728

__global__ __launch_bounds__(256, 2) void attn_mma(
    const __half* __restrict__ qkv, __half* __restrict__ oh)
{
    extern __shared__ char smem[];
    const uint32_t sb = smem_to_u32(smem);
    const int tid  = threadIdx.x;
    const int w    = tid >> 5;
    const int lane = tid & 31;
    const int bh = blockIdx.y;
    const int b  = bh >> 4;
    const int h  = bh & 15;
    const int q0 = blockIdx.x * 128;

    const uint32_t QHs = sb;

    {
        const int r  = tid >> 1;
        const int cb = (tid & 1) * 4;
        const size_t g = (size_t)(b * SEQ + q0 + r) * D3 + h * HDIM + cb * 8;
        const uint32_t o = r * AROW + cb * 16;
        #pragma unroll
        for (int c = 0; c < 4; c++)
            cp16(QHs + o + c * 16, qkv + g + c * 8);
    }
    auto load_kv = [&](int kt, int s) {
        const uint32_t st = sb + AQ_BYTES + s * AST + (tid >> 7) * KV_TILE;
        const int t2 = tid & 127;
        const int r  = t2 >> 1;
        const int cb = (t2 & 1) * 4;
        const size_t g = (size_t)(b * SEQ + kt * 64 + r) * D3 + DMODEL
                       + (tid >> 7) * DMODEL + h * HDIM + cb * 8;
        const uint32_t o = r * AROW + cb * 16;
        #pragma unroll
        for (int c = 0; c < 4; c++)
            cp16(st + o + c * 16, qkv + g + c * 8);
    };
    load_kv(0, 0); CP_COMMIT();
    load_kv(1, 1); CP_COMMIT();

    uint32_t qfh[4][4];
    float O[8][4];
    #pragma unroll
    for (int i = 0; i < 8; i++)
        #pragma unroll
        for (int j = 0; j < 4; j++) O[i][j] = 0.0f;
    float m0 = -1e30f, m1 = -1e30f, l0 = 0.0f, l1 = 0.0f;

    for (int kt = 0; kt < SEQ / 64; kt++) {
        CP_WAIT1();
        __syncthreads();
        if (kt == 0) {
            #pragma unroll
            for (int kf = 0; kf < 4; kf++) {
                uint32_t qa = QHs + (w * 16 + (lane & 15)) * AROW + kf * 32 + (lane >> 4) * 16;
                ldsm4(qfh[kf], qa);
            }
        }
        const uint32_t st = sb + AQ_BYTES + (kt % ATT_NSTAGE) * AST;

        // ---- S = Q K^T ----
        float s[8][4];
        #pragma unroll
        for (int i = 0; i < 8; i++)
            #pragma unroll
            for (int j = 0; j < 4; j++) s[i][j] = 0.0f;
        #pragma unroll
        for (int kf = 0; kf < 4; kf++) {
            const int kbB = kf * 32 + ((lane >> 3) & 1) * 16;
            #pragma unroll
            for (int np = 0; np < 4; np++) {
                uint32_t ka = st
                    + ((np * 2 + ((lane >> 4) & 1)) * 8 + (lane & 7)) * AROW + kbB;
                uint32_t d[4];
                ldsm4(d, ka);
                mma16816(s[np * 2],     qfh[kf], d);
                mma16816(s[np * 2 + 1], qfh[kf], d + 2);
            }
        }

        // ---- online softmax ----
        float mx0 = -1e30f, mx1 = -1e30f;
        #pragma unroll
        for (int nf = 0; nf < 8; nf++) {
            s[nf][0] *= 0.125f; s[nf][1] *= 0.125f;
            s[nf][2] *= 0.125f; s[nf][3] *= 0.125f;
            mx0 = fmaxf(mx0, fmaxf(s[nf][0], s[nf][1]));
            mx1 = fmaxf(mx1, fmaxf(s[nf][2], s[nf][3]));
        }
        mx0 = fmaxf(mx0, __shfl_xor_sync(0xffffffffu, mx0, 1));
        mx0 = fmaxf(mx0, __shfl_xor_sync(0xffffffffu, mx0, 2));
        mx1 = fmaxf(mx1, __shfl_xor_sync(0xffffffffu, mx1, 1));
        mx1 = fmaxf(mx1, __shfl_xor_sync(0xffffffffu, mx1, 2));
        float mn0 = fmaxf(m0, mx0), mn1 = fmaxf(m1, mx1);
        float cr0 = __expf(m0 - mn0), cr1 = __expf(m1 - mn1);
        float sm0 = 0.0f, sm1 = 0.0f;
        #pragma unroll
        for (int nf = 0; nf < 8; nf++) {
            s[nf][0] = __expf(s[nf][0] - mn0); sm0 += s[nf][0];
            s[nf][1] = __expf(s[nf][1] - mn0); sm0 += s[nf][1];
            s[nf][2] = __expf(s[nf][2] - mn1); sm1 += s[nf][2];
            s[nf][3] = __expf(s[nf][3] - mn1); sm1 += s[nf][3];
        }
        sm0 += __shfl_xor_sync(0xffffffffu, sm0, 1);
        sm0 += __shfl_xor_sync(0xffffffffu, sm0, 2);
        sm1 += __shfl_xor_sync(0xffffffffu, sm1, 1);
        sm1 += __shfl_xor_sync(0xffffffffu, sm1, 2);
        l0 = l0 * cr0 + sm0; m0 = mn0;
        l1 = l1 * cr1 + sm1; m1 = mn1;
        #pragma unroll
        for (int nf = 0; nf < 8; nf++) {
            O[nf][0] *= cr0; O[nf][1] *= cr0;
            O[nf][2] *= cr1; O[nf][3] *= cr1;
        }

        // ---- O += P V  (paired ldsm4.trans: two d-tiles per load) ----
        #pragma unroll
        for (int kf = 0; kf < 4; kf++) {
            uint32_t pa[4];
            pa[0] = pack2h(s[2*kf][0],   s[2*kf][1]);
            pa[1] = pack2h(s[2*kf][2],   s[2*kf][3]);
            pa[2] = pack2h(s[2*kf+1][0], s[2*kf+1][1]);
            pa[3] = pack2h(s[2*kf+1][2], s[2*kf+1][3]);
            #pragma unroll
            for (int np = 0; np < 4; np++) {
                uint32_t va = st + KV_TILE + (kf * 16 + (lane & 15)) * AROW
                            + (np * 2 + ((lane >> 4) & 1)) * 16;
                uint32_t d[4];
                ldsm4t(d, va);
                mma16816(O[np * 2],     pa, d);
                mma16816(O[np * 2 + 1], pa, d + 2);
            }
        }

        __syncthreads();
        if (kt + 2 < SEQ / 64) load_kv(kt + 2, (kt + 2) % ATT_NSTAGE);
        CP_COMMIT();
    }

    // ---- write ctx fp16 ----
    {
        float i0 = 1.0f / l0, i1 = 1.0f / l1;
        const int mr = q0 + w * 16 + (lane >> 2);
        const size_t row0 = (size_t)(b * SEQ + mr) * DMODEL;
        const size_t row1 = row0 + 8 * DMODEL;
        #pragma unroll
        for (int nf = 0; nf < 8; nf++) {
            const int n = h * HDIM + nf * 8 + (lane & 3) * 2;
            *(uint32_t*)(oh + row0 + n) = pack2h(O[nf][0] * i0, O[nf][1] * i0);
            *(uint32_t*)(oh + row1 + n) = pack2h(O[nf][2] * i1, O[nf][3] * i1);
        }
    }
}

// ----------------------------------------------------------------------------
// LayerNorm; SPLIT=1 additionally emits fp16 of the output
// ----------------------------------------------------------------------------
template <int SPLIT>
__global__ __launch_bounds__(256) void ln_kernel(
    const float* __restrict__ x, const float* __restrict__ g,
    const float* __restrict__ beta, float* __restrict__ y,
    __half* __restrict__ yh)
{
    const int row = blockIdx.x;
    const int tid = threadIdx.x;
    const float* xr = x + (size_t)row * DMODEL;

    float4 v = *(const float4*)(xr + tid * 4);
    float s  = v.x + v.y + v.z + v.w;
    float sq = v.x*v.x + v.y*v.y + v.z*v.z + v.w*v.w;

    #pragma unroll
    for (int off = 16; off > 0; off >>= 1) {
        s  += __shfl_xor_sync(0xffffffffu, s,  off);
        sq += __shfl_xor_sync(0xffffffffu, sq, off);
    }
    __shared__ float ss[8], ssq[8];
    if ((tid & 31) == 0) { ss[tid >> 5] = s; ssq[tid >> 5] = sq; }
    __syncthreads();
    float tot = 0.0f, totq = 0.0f;
    #pragma unroll
    for (int i = 0; i < 8; i++) { tot += ss[i]; totq += ssq[i]; }

    const float mu   = tot * (1.0f / DMODEL);
    const float var  = totq * (1.0f / DMODEL) - mu * mu;
    const float rstd = rsqrtf(var + 1e-5f);

    float4 gg = *(const float4*)(g + tid * 4);
    float4 bb = *(const float4*)(beta + tid * 4);
    float4 o;
    o.x = (v.x - mu) * rstd * gg.x + bb.x;
    o.y = (v.y - mu) * rstd * gg.y + bb.y;
    o.z = (v.z - mu) * rstd * gg.z + bb.z;
    o.w = (v.w - mu) * rstd * gg.w + bb.w;
    *(float4*)(y + (size_t)row * DMODEL + tid * 4) = o;

    if (SPLIT) {
        ((uint2*)(yh + (size_t)row * DMODEL))[tid] =
            make_uint2(pack2h(o.x, o.y), pack2h(o.z, o.w));
    }
}

// ----------------------------------------------------------------------------
// kernel_launch
// Inputs: 0 X, 1 W_qkv, 2 b_qkv, 3 W_out, 4 b_out, 5 ln1_g, 6 ln1_b,
//         7 ln2_g, 8 ln2_b, 9 W_ff1, 10 b_ff1, 11 W_ff2, 12 b_ff2
// ----------------------------------------------------------------------------
extern "C" void kernel_launch(void* const* d_in, const int* in_sizes, int n_in,
                              void* d_out, int out_size)
{
    const float* X      = (const float*)d_in[0];
    const float* W_qkv  = (const float*)d_in[1];
    const float* b_qkv  = (const float*)d_in[2];
    const float* W_out  = (const float*)d_in[3];
    const float* b_out  = (const float*)d_in[4];
    const float* ln1_g  = (const float*)d_in[5];
    const float* ln1_b  = (const float*)d_in[6];
    const float* ln2_g  = (const float*)d_in[7];
    const float* ln2_b  = (const float*)d_in[8];
    const float* W_ff1  = (const float*)d_in[9];
    const float* b_ff1  = (const float*)d_in[10];
    const float* W_ff2  = (const float*)d_in[11];
    const float* b_ff2  = (const float*)d_in[12];
    float* out = (float*)d_out;

    float *tmp, *x1;
    __half *qkh, *ah, *fh;
    __half *wqh, *woh, *w1h, *w2h;
    cudaGetSymbolAddress((void**)&qkh, g_qkv_h);
    cudaGetSymbolAddress((void**)&tmp, g_tmp);
    cudaGetSymbolAddress((void**)&x1,  g_x1);
    cudaGetSymbolAddress((void**)&ah,  g_act_h);
    cudaGetSymbolAddress((void**)&fh,  g_ffh_h);
    cudaGetSymbolAddress((void**)&wqh, g_wqkv_h);
    cudaGetSymbolAddress((void**)&woh, g_wout_h);
    cudaGetSymbolAddress((void**)&w1h, g_wff1_h);
    cudaGetSymbolAddress((void**)&w2h, g_wff2_h);

    cudaFuncSetAttribute(gemm_mma<1>, cudaFuncAttributeMaxDynamicSharedMemorySize, GEMM_SMEM);
    cudaFuncSetAttribute(gemm_mma<2>, cudaFuncAttributeMaxDynamicSharedMemorySize, GEMM_SMEM);
    cudaFuncSetAttribute(gemm_mma<3>, cudaFuncAttributeMaxDynamicSharedMemorySize, GEMM_SMEM);
    cudaFuncSetAttribute(attn_mma, cudaFuncAttributeMaxDynamicSharedMemorySize, ATT_SMEM);

    // 0) fused weight transposes + X fp16 convert (one launch)
    prep_kernel<<<PREP_TILES + CONV_BLOCKS, 256>>>(
        W_qkv, W_out, W_ff1, W_ff2, X, wqh, woh, w1h, w2h, ah);

    // 1) QKV projection -> fp16
    gemm_mma<3><<<dim3(D3 / BN, M_ROWS / BM), 256, GEMM_SMEM>>>(
        ah, wqh, b_qkv, nullptr, nullptr, qkh, D3, DMODEL);

    // 2) tensor-core attention -> ctx fp16 (reuses act buffer)
    attn_mma<<<dim3(SEQ / 128, 8 * NHEAD), 256, ATT_SMEM>>>(qkh, ah);

    // 3) out-proj + residual(X) -> tmp fp32
    gemm_mma<1><<<dim3(DMODEL / BN, M_ROWS / BM), 256, GEMM_SMEM>>>(
        ah, woh, b_out, X, tmp, nullptr, DMODEL, DMODEL);

    // 4) LN1 -> x1 fp32 + fp16
    ln_kernel<1><<<M_ROWS, 256>>>(tmp, ln1_g, ln1_b, x1, ah);

    // 5) FF1 + GELU -> fp16
    gemm_mma<2><<<dim3(DFF / BN, M_ROWS / BM), 256, GEMM_SMEM>>>(
        ah, w1h, b_ff1, nullptr, nullptr, fh, DFF, DMODEL);

    // 6) FF2 + residual(x1) -> tmp fp32
    gemm_mma<1><<<dim3(DMODEL / BN, M_ROWS / BM), 256, GEMM_SMEM>>>(
        fh, w2h, b_ff2, x1, tmp, nullptr, DMODEL, DFF);

    // 7) LN2 -> out
    ln_kernel<0><<<M_ROWS, 256>>>(tmp, ln2_g, ln2_b, out, nullptr);
}